// round 11
// baseline (speedup 1.0000x reference)
#include <cuda_runtime.h>
#include <cstdint>

#define N_EDGES 250000
#define N_RBF   10
#define FEAT    144
#define P_TOTAL 4864
#define TILE_E  32
#define THREADS 256
#define NWARP   (THREADS / 32)          // 8
#define VSTRIDE 16                      // Rt w-row stride (no padding; GMEM now)
#define RSLICE  (16 * VSTRIDE)          // 256 floats per r-slice
#define RBUF    (N_RBF * RSLICE)        // 2560 floats per path slice
#define YS_STR  40                      // padded Ys per-edge stride
#define TMP_ESTR 88                     // tmp per-edge stride
#define TMP_WARP (4 * TMP_ESTR)         // 352 floats per warp
#define RADS_WARP 80                    // per-warp radial table
#define NPATH   19

typedef unsigned long long u64;

__constant__ float cg_c[1225];
__device__ float R_pad[NPATH * RBUF];   // transposed + norm-folded R (194.6 kB)

// ---- packed f32x2 helpers -------------------------------------------------
__device__ __forceinline__ u64 pack2(float lo, float hi) {
    u64 r; asm("mov.b64 %0, {%1,%2};" : "=l"(r) : "f"(lo), "f"(hi)); return r;
}
__device__ __forceinline__ void unpack2(u64 v, float& lo, float& hi) {
    asm("mov.b64 {%0,%1}, %2;" : "=f"(lo), "=f"(hi) : "l"(v));
}
__device__ __forceinline__ u64 ffma2(u64 a, u64 b, u64 c) {
    u64 d; asm("fma.rn.f32x2 %0, %1, %2, %3;" : "=l"(d) : "l"(a), "l"(b), "l"(c));
    return d;
}
__device__ __forceinline__ u64 fmul2(u64 a, u64 b) {
    u64 d; asm("mul.rn.f32x2 %0, %1, %2;" : "=l"(d) : "l"(a), "l"(b)); return d;
}
__device__ __forceinline__ u64 fadd2(u64 a, u64 b) {
    u64 d; asm("add.rn.f32x2 %0, %1, %2;" : "=l"(d) : "l"(a), "l"(b)); return d;
}

// ---------------------------------------------------------------------------
// Prep: R -> R_pad[p][r][w*16 + v], 1/sqrt(df) folded in.
// ---------------------------------------------------------------------------
__global__ void prep_kernel(const float* __restrict__ R)
{
    const float norms[NPATH] = {
        1.0f, 0.57735026918962576f, 0.44721359549995794f,
        0.57735026918962576f, 1.0f, 0.57735026918962576f,
        0.44721359549995794f, 0.57735026918962576f,
        0.44721359549995794f, 0.37796447300922723f,
        0.44721359549995794f, 0.57735026918962576f,
        0.44721359549995794f, 0.37796447300922723f, 1.0f,
        0.57735026918962576f, 0.44721359549995794f,
        0.37796447300922723f, 0.33333333333333333f
    };
    int idx = blockIdx.x * blockDim.x + threadIdx.x;
    if (idx >= NPATH * RBUF) return;
    int p   = idx / RBUF, rem = idx - p * RBUF;
    int r   = rem / RSLICE, c = rem - r * RSLICE;   // c = w*16 + v
    R_pad[idx] = R[(size_t)r * P_TOTAL + p * 256 + c] * norms[p];
}

// ---------------------------------------------------------------------------
// One path, f32x2-packed. No block barriers: R comes straight from L1-resident
// R_pad via LDG.128; tmp exchange uses per-warp smem + __syncwarp only.
// ---------------------------------------------------------------------------
template<int IO, int II, int LF, int CGOFF>
__device__ __forceinline__ void do_path(
    const u64 (&FAB)[9],
    const float* __restrict__ Ys_p,
    const float* __restrict__ Rt,       // global: R_pad + path*RBUF
    float* __restrict__ tmp_w,
    const float* __restrict__ radS_w,
    int m, int eh, int lA, int lB, int leA,
    u64 (&acc)[4][5])
{
    constexpr int DOUT = 2 * IO + 1;
    constexpr int DI   = 2 * II + 1;
    constexpr int DF   = 2 * LF + 1;
    constexpr int FB0  = (II == 0) ? 0 : ((II == 1) ? 1 : 4);
    constexpr int YB   = (LF == 0) ? 0 : (LF == 1) ? 4 : (LF == 2) ? 12
                       : (LF == 3) ? 20 : 28;

    // ---- packed Ys ----
    u64 yAB[DF];
    {
        float ya[DF], yb[DF];
        const float* pa = Ys_p + lA * YS_STR + YB;
        const float* pb = Ys_p + lB * YS_STR + YB;
#pragma unroll
        for (int f4 = 0; f4 < DF / 4; f4++) {
            float4 qa = *(const float4*)(pa + 4 * f4);
            float4 qb = *(const float4*)(pb + 4 * f4);
            ya[4*f4+0]=qa.x; ya[4*f4+1]=qa.y; ya[4*f4+2]=qa.z; ya[4*f4+3]=qa.w;
            yb[4*f4+0]=qb.x; yb[4*f4+1]=qb.y; yb[4*f4+2]=qb.z; yb[4*f4+3]=qb.w;
        }
#pragma unroll
        for (int f = (DF / 4) * 4; f < DF; f++) { ya[f] = pa[f]; yb[f] = pb[f]; }
#pragma unroll
        for (int f = 0; f < DF; f++) yAB[f] = pack2(ya[f], yb[f]);
    }

    // ---- packed tmp[v=m][o] for the (A,B) pair ----
    u64 tAB[DOUT];
#pragma unroll
    for (int o = 0; o < DOUT; o++) tAB[o] = 0ull;

#pragma unroll
    for (int f = 0; f < DF; f++) {
#pragma unroll
        for (int o = 0; o < DOUT; o++) {
            float c0 = cg_c[CGOFF + (o * DI + 0) * DF + f];
            u64 g = fmul2(FAB[FB0], pack2(c0, c0));
#pragma unroll
            for (int i = 1; i < DI; i++) {
                float c = cg_c[CGOFF + (o * DI + i) * DF + f];
                g = ffma2(FAB[FB0 + i], pack2(c, c), g);
            }
            tAB[o] = ffma2(yAB[f], g, tAB[o]);
        }
    }

    // ---- publish tmp scalars to warp scratch ----
    __syncwarp();
#pragma unroll
    for (int o = 0; o < DOUT; o++) {
        float lo, hi; unpack2(tAB[o], lo, hi);
        tmp_w[ leA      * TMP_ESTR + o * 16 + m] = lo;
        tmp_w[(leA + 1) * TMP_ESTR + o * 16 + m] = hi;
    }
    __syncwarp();

    // ---- W: r-outer; Rt rows read as LDG.128 (L1-resident R_pad) ----
    const float* row = Rt + m * VSTRIDE + eh * 8;
    u64 wP[4][2][2];
#pragma unroll
    for (int j = 0; j < 4; j++)
#pragma unroll
        for (int g = 0; g < 2; g++) { wP[j][g][0] = 0ull; wP[j][g][1] = 0ull; }

#pragma unroll
    for (int r = 0; r < N_RBF; r++) {
        float4 rd0 = *(const float4*)(radS_w + r * 8);
        float4 rd1 = *(const float4*)(radS_w + r * 8 + 4);
        u64 d0 = pack2(rd0.x, rd0.y);
        u64 d1 = pack2(rd0.z, rd0.w);
        u64 d2 = pack2(rd1.x, rd1.y);
        u64 d3 = pack2(rd1.z, rd1.w);
        float4 q0 = *(const float4*)(row + r * RSLICE);       // LDG.128
        float4 q1 = *(const float4*)(row + r * RSLICE + 4);   // LDG.128
        u64 q00 = pack2(q0.x, q0.y), q01 = pack2(q0.z, q0.w);
        u64 q10 = pack2(q1.x, q1.y), q11 = pack2(q1.z, q1.w);
        wP[0][0][0] = ffma2(d0, q00, wP[0][0][0]);
        wP[0][0][1] = ffma2(d0, q01, wP[0][0][1]);
        wP[0][1][0] = ffma2(d0, q10, wP[0][1][0]);
        wP[0][1][1] = ffma2(d0, q11, wP[0][1][1]);
        wP[1][0][0] = ffma2(d1, q00, wP[1][0][0]);
        wP[1][0][1] = ffma2(d1, q01, wP[1][0][1]);
        wP[1][1][0] = ffma2(d1, q10, wP[1][1][0]);
        wP[1][1][1] = ffma2(d1, q11, wP[1][1][1]);
        wP[2][0][0] = ffma2(d2, q00, wP[2][0][0]);
        wP[2][0][1] = ffma2(d2, q01, wP[2][0][1]);
        wP[2][1][0] = ffma2(d2, q10, wP[2][1][0]);
        wP[2][1][1] = ffma2(d2, q11, wP[2][1][1]);
        wP[3][0][0] = ffma2(d3, q00, wP[3][0][0]);
        wP[3][0][1] = ffma2(d3, q01, wP[3][0][1]);
        wP[3][1][0] = ffma2(d3, q10, wP[3][1][0]);
        wP[3][1][1] = ffma2(d3, q11, wP[3][1][1]);
    }

    // ---- apply ----
#pragma unroll
    for (int g = 0; g < 2; g++) {
        const int v0 = eh * 8 + g * 4;
#pragma unroll
        for (int j = 0; j < 4; j++) {
#pragma unroll
            for (int o = 0; o < DOUT; o++) {
                float4 tf = *(const float4*)(tmp_w + j * TMP_ESTR + o * 16 + v0);
                u64 t01 = pack2(tf.x, tf.y), t23 = pack2(tf.z, tf.w);
                acc[j][o] = ffma2(wP[j][g][0], t01, acc[j][o]);
                acc[j][o] = ffma2(wP[j][g][1], t23, acc[j][o]);
            }
        }
    }
}

// ---------------------------------------------------------------------------
__global__ void __launch_bounds__(THREADS, 2)
conv_kernel(const float* __restrict__ features,
            const float* __restrict__ Ys,
            const float* __restrict__ radii,
            const float* __restrict__ n_norm,
            const int*   __restrict__ map_a,
            const int*   __restrict__ map_b,
            float* __restrict__ out)
{
    __shared__ __align__(16) float tmp_s[NWARP * TMP_WARP];  // 11.3 kB
    __shared__ __align__(16) float Ys_p[TILE_E * YS_STR];    //  5.1 kB
    __shared__ __align__(16) float radS[NWARP * RADS_WARP];  //  2.6 kB

    const int tid  = threadIdx.x;
    const int warp = tid >> 5;
    const int lane = tid & 31;
    const int m    = lane & 15;
    const int eh   = lane >> 4;
    const int e0   = blockIdx.x * TILE_E;
    const int leA  = eh * 2;
    const int lA   = warp * 4 + leA;
    const int lB   = lA + 1;
    float* tmp_w   = tmp_s + warp * TMP_WARP;
    const float* radS_w = radS + warp * RADS_WARP;

    // ---- stage padded Ys ----
    for (int idx = tid; idx < TILE_E * 25; idx += THREADS) {
        int le = idx / 25, f = idx - le * 25;
        int e  = e0 + le;
        int off = (f < 1) ? f : (f < 4) ? 3 + f : (f < 9) ? 8 + f
                : (f < 16) ? 11 + f : 12 + f;
        Ys_p[le * YS_STR + off] = (e < N_EDGES) ? Ys[(size_t)e * 25 + f] : 0.f;
    }

    // ---- per-warp duplicated radial table ----
    for (int idx = lane; idx < RADS_WARP; idx += 32) {
        int r = idx >> 3, j = (idx & 7) >> 1;
        int e = e0 + warp * 4 + j;
        bool v = (e < N_EDGES);
        radS[warp * RADS_WARP + idx] =
            v ? radii[(size_t)(v ? e : 0) * N_RBF + r] : 0.f;
    }

    // ---- per-lane bindings ----
    const int eA = e0 + lA, eB = e0 + lB;
    const bool vA = (eA < N_EDGES), vB = (eB < N_EDGES);
    const int eAc = vA ? eA : 0, eBc = vB ? eB : 0;

    u64 FAB[9];
    {
        const float* fA = features + (size_t)map_b[eAc] * FEAT;
        const float* fB = features + (size_t)map_b[eBc] * FEAT;
        FAB[0] = pack2(fA[m], fB[m]);
#pragma unroll
        for (int i = 0; i < 3; i++)
            FAB[1 + i] = pack2(fA[16 + m * 3 + i], fB[16 + m * 3 + i]);
#pragma unroll
        for (int i = 0; i < 5; i++)
            FAB[4 + i] = pack2(fA[64 + m * 5 + i], fB[64 + m * 5 + i]);
    }

    const int   aA  = map_a[eAc];
    const int   aB  = map_a[eBc];
    const float nnA = vA ? n_norm[aA] : 0.f;
    const float nnB = vB ? n_norm[aB] : 0.f;

    u64 acc[4][5];
#pragma unroll
    for (int j = 0; j < 4; j++)
#pragma unroll
        for (int o = 0; o < 5; o++) acc[j][o] = 0ull;

    __syncthreads();   // Ys_p, radS visible (only block-wide barrier)

#define DO(P, IO, II, LF, CGOFF)                                               \
    do_path<IO, II, LF, CGOFF>(FAB, Ys_p, R_pad + (size_t)(P) * RBUF,          \
                               tmp_w, radS_w, m, eh, lA, lB, leA, acc)

#define EMIT(DOUT, EXPR_IDX)                                                   \
    do {                                                                       \
        float tot[4][DOUT];                                                    \
        _Pragma("unroll")                                                      \
        for (int j = 0; j < 4; j++)                                            \
            _Pragma("unroll")                                                  \
            for (int o = 0; o < (DOUT); o++) {                                 \
                u64 s = fadd2(acc[j][o],                                       \
                              __shfl_xor_sync(0xffffffffu, acc[j][o], 16));    \
                float lo, hi; unpack2(s, lo, hi);                              \
                tot[j][o] = lo + hi;                                           \
            }                                                                  \
        _Pragma("unroll")                                                      \
        for (int o = 0; o < (DOUT); o++) {                                     \
            if (vA) atomicAdd(&out[(size_t)aA * FEAT + (EXPR_IDX)],            \
                              nnA * tot[leA][o]);                              \
            if (vB) atomicAdd(&out[(size_t)aB * FEAT + (EXPR_IDX)],            \
                              nnB * tot[leA + 1][o]);                          \
        }                                                                      \
    } while (0)

#define CLEAR()                                                                \
    do {                                                                       \
        _Pragma("unroll")                                                      \
        for (int j = 0; j < 4; j++)                                            \
            _Pragma("unroll")                                                  \
            for (int o = 0; o < 5; o++) acc[j][o] = 0ull;                      \
    } while (0)

    // ---------------- io = 0 (DOUT = 1, out offset 0) -----------------------
    DO(0, 0, 0, 0, 0);
    DO(1, 0, 1, 1, 1);
    DO(2, 0, 2, 2, 10);
    EMIT(1, m);
    CLEAR();

    // ---------------- io = 1 (DOUT = 3, out offset 16) ----------------------
    DO(3, 1, 0, 1, 35);
    DO(4, 1, 1, 0, 44);
    DO(5, 1, 1, 1, 53);
    DO(6, 1, 1, 2, 80);
    DO(7, 1, 2, 1, 125);
    DO(8, 1, 2, 2, 170);
    DO(9, 1, 2, 3, 245);
    EMIT(3, 16 + m * 3 + o);
    CLEAR();

    // ---------------- io = 2 (DOUT = 5, out offset 64) ----------------------
    DO(10, 2, 0, 2, 350);
    DO(11, 2, 1, 1, 375);
    DO(12, 2, 1, 2, 420);
    DO(13, 2, 1, 3, 495);
    DO(14, 2, 2, 0, 600);
    DO(15, 2, 2, 1, 625);
    DO(16, 2, 2, 2, 700);
    DO(17, 2, 2, 3, 825);
    DO(18, 2, 2, 4, 1000);
    EMIT(5, 64 + m * 5 + o);

#undef DO
#undef EMIT
#undef CLEAR
}

// ---------------------------------------------------------------------------
extern "C" void kernel_launch(void* const* d_in, const int* in_sizes, int n_in,
                              void* d_out, int out_size)
{
    const float* features = (const float*)d_in[0];
    const float* R        = (const float*)d_in[1];
    const float* Ys       = (const float*)d_in[2];
    const float* radii    = (const float*)d_in[3];
    const float* cg       = (const float*)d_in[4];
    const float* n_norm   = (const float*)d_in[5];
    const int*   map_a    = (const int*)d_in[6];
    const int*   map_b    = (const int*)d_in[7];
    float*       out      = (float*)d_out;

    cudaMemcpyToSymbolAsync(cg_c, cg, 1225 * sizeof(float), 0,
                            cudaMemcpyDeviceToDevice, 0);
    cudaMemsetAsync(out, 0, (size_t)out_size * sizeof(float));

    prep_kernel<<<(NPATH * RBUF + 255) / 256, 256>>>(R);

    int grid = (N_EDGES + TILE_E - 1) / TILE_E;   // 7813
    conv_kernel<<<grid, THREADS>>>(features, Ys, radii, n_norm,
                                   map_a, map_b, out);
}

// round 12
// speedup vs baseline: 1.7786x; 1.7786x over previous
#include <cuda_runtime.h>
#include <cstdint>

#define N_EDGES 250000
#define N_RBF   10
#define FEAT    144
#define P_TOTAL 4864
#define TILE_E  32
#define THREADS 256
#define NWARP   (THREADS / 32)          // 8
#define VSTRIDE 20                      // Rt w-row stride (16 used + 4 pad)
#define RSLICE  (16 * VSTRIDE)          // 320 floats per r-slice
#define RBUF    (N_RBF * RSLICE)        // 3200 floats per path slice
#define YS_STR  40                      // padded Ys per-edge stride
#define TMP_ESTR 88                     // tmp per-edge stride
#define TMP_WARP (4 * TMP_ESTR)         // 352 floats per warp
#define RADS_WARP 80                    // per-warp radial table
#define NPATH   19

// dynamic smem partition (floats): ring of 4 single-path R buffers
#define OFF_RT   0
#define OFF_TMP  (OFF_RT + 4 * RBUF)                 // 12800
#define OFF_YS   (OFF_TMP + NWARP * TMP_WARP)        // 15616
#define OFF_RAD  (OFF_YS + TILE_E * YS_STR)          // 16896
#define SMEM_FLOATS (OFF_RAD + NWARP * RADS_WARP)    // 17536
#define SMEM_BYTES  (SMEM_FLOATS * 4)                // 70144

typedef unsigned long long u64;

__constant__ float cg_c[1225];
__device__ float R_pad[NPATH * RBUF];   // padded+transposed+norm-folded R

// ---- packed f32x2 helpers -------------------------------------------------
__device__ __forceinline__ u64 pack2(float lo, float hi) {
    u64 r; asm("mov.b64 %0, {%1,%2};" : "=l"(r) : "f"(lo), "f"(hi)); return r;
}
__device__ __forceinline__ void unpack2(u64 v, float& lo, float& hi) {
    asm("mov.b64 {%0,%1}, %2;" : "=f"(lo), "=f"(hi) : "l"(v));
}
__device__ __forceinline__ u64 ffma2(u64 a, u64 b, u64 c) {
    u64 d; asm("fma.rn.f32x2 %0, %1, %2, %3;" : "=l"(d) : "l"(a), "l"(b), "l"(c));
    return d;
}
__device__ __forceinline__ u64 fmul2(u64 a, u64 b) {
    u64 d; asm("mul.rn.f32x2 %0, %1, %2;" : "=l"(d) : "l"(a), "l"(b)); return d;
}
__device__ __forceinline__ u64 fadd2(u64 a, u64 b) {
    u64 d; asm("add.rn.f32x2 %0, %1, %2;" : "=l"(d) : "l"(a), "l"(b)); return d;
}

// ---------------------------------------------------------------------------
// Prep: relayout R into R_pad[p][r][w*VSTRIDE + v] with 1/sqrt(df) folded in.
// ---------------------------------------------------------------------------
__global__ void prep_kernel(const float* __restrict__ R)
{
    const float norms[NPATH] = {
        1.0f, 0.57735026918962576f, 0.44721359549995794f,
        0.57735026918962576f, 1.0f, 0.57735026918962576f,
        0.44721359549995794f, 0.57735026918962576f,
        0.44721359549995794f, 0.37796447300922723f,
        0.44721359549995794f, 0.57735026918962576f,
        0.44721359549995794f, 0.37796447300922723f, 1.0f,
        0.57735026918962576f, 0.44721359549995794f,
        0.37796447300922723f, 0.33333333333333333f
    };
    int idx = blockIdx.x * blockDim.x + threadIdx.x;
    if (idx >= NPATH * RBUF) return;
    int p    = idx / RBUF,   rem  = idx - p * RBUF;
    int r    = rem / RSLICE; int rem2 = rem - r * RSLICE;
    int w    = rem2 / VSTRIDE, v = rem2 - w * VSTRIDE;
    float val = 0.f;
    if (v < 16)
        val = R[(size_t)r * P_TOTAL + p * 256 + w * 16 + v] * norms[p];
    R_pad[idx] = val;
}

// ---------------------------------------------------------------------------
// One path, f32x2-packed (identical to R8 champion).
// ---------------------------------------------------------------------------
template<int IO, int II, int LF, int CGOFF>
__device__ __forceinline__ void do_path(
    const u64 (&FAB)[9],
    const float* __restrict__ Ys_p,
    const float* __restrict__ Rt,
    float* __restrict__ tmp_w,
    const float* __restrict__ radS_w,
    int m, int eh, int lA, int lB, int leA,
    u64 (&acc)[4][5])
{
    constexpr int DOUT = 2 * IO + 1;
    constexpr int DI   = 2 * II + 1;
    constexpr int DF   = 2 * LF + 1;
    constexpr int FB0  = (II == 0) ? 0 : ((II == 1) ? 1 : 4);
    constexpr int YB   = (LF == 0) ? 0 : (LF == 1) ? 4 : (LF == 2) ? 12
                       : (LF == 3) ? 20 : 28;

    // ---- packed Ys ----
    u64 yAB[DF];
    {
        float ya[DF], yb[DF];
        const float* pa = Ys_p + lA * YS_STR + YB;
        const float* pb = Ys_p + lB * YS_STR + YB;
#pragma unroll
        for (int f4 = 0; f4 < DF / 4; f4++) {
            float4 qa = *(const float4*)(pa + 4 * f4);
            float4 qb = *(const float4*)(pb + 4 * f4);
            ya[4*f4+0]=qa.x; ya[4*f4+1]=qa.y; ya[4*f4+2]=qa.z; ya[4*f4+3]=qa.w;
            yb[4*f4+0]=qb.x; yb[4*f4+1]=qb.y; yb[4*f4+2]=qb.z; yb[4*f4+3]=qb.w;
        }
#pragma unroll
        for (int f = (DF / 4) * 4; f < DF; f++) { ya[f] = pa[f]; yb[f] = pb[f]; }
#pragma unroll
        for (int f = 0; f < DF; f++) yAB[f] = pack2(ya[f], yb[f]);
    }

    // ---- packed tmp[v=m][o] for the (A,B) pair ----
    u64 tAB[DOUT];
#pragma unroll
    for (int o = 0; o < DOUT; o++) tAB[o] = 0ull;

#pragma unroll
    for (int f = 0; f < DF; f++) {
#pragma unroll
        for (int o = 0; o < DOUT; o++) {
            float c0 = cg_c[CGOFF + (o * DI + 0) * DF + f];
            u64 g = fmul2(FAB[FB0], pack2(c0, c0));
#pragma unroll
            for (int i = 1; i < DI; i++) {
                float c = cg_c[CGOFF + (o * DI + i) * DF + f];
                g = ffma2(FAB[FB0 + i], pack2(c, c), g);
            }
            tAB[o] = ffma2(yAB[f], g, tAB[o]);
        }
    }

    // ---- publish tmp scalars to warp scratch ----
    __syncwarp();
#pragma unroll
    for (int o = 0; o < DOUT; o++) {
        float lo, hi; unpack2(tAB[o], lo, hi);
        tmp_w[ leA      * TMP_ESTR + o * 16 + m] = lo;
        tmp_w[(leA + 1) * TMP_ESTR + o * 16 + m] = hi;
    }
    __syncwarp();

    // ---- W: r-outer, radS loads hoisted across both v-quads ----
    const float* row = Rt + m * VSTRIDE + eh * 8;
    u64 wP[4][2][2];
#pragma unroll
    for (int j = 0; j < 4; j++)
#pragma unroll
        for (int g = 0; g < 2; g++) { wP[j][g][0] = 0ull; wP[j][g][1] = 0ull; }

#pragma unroll
    for (int r = 0; r < N_RBF; r++) {
        float4 rd0 = *(const float4*)(radS_w + r * 8);
        float4 rd1 = *(const float4*)(radS_w + r * 8 + 4);
        u64 d0 = pack2(rd0.x, rd0.y);
        u64 d1 = pack2(rd0.z, rd0.w);
        u64 d2 = pack2(rd1.x, rd1.y);
        u64 d3 = pack2(rd1.z, rd1.w);
        float4 q0 = *(const float4*)(row + r * RSLICE);
        float4 q1 = *(const float4*)(row + r * RSLICE + 4);
        u64 q00 = pack2(q0.x, q0.y), q01 = pack2(q0.z, q0.w);
        u64 q10 = pack2(q1.x, q1.y), q11 = pack2(q1.z, q1.w);
        wP[0][0][0] = ffma2(d0, q00, wP[0][0][0]);
        wP[0][0][1] = ffma2(d0, q01, wP[0][0][1]);
        wP[0][1][0] = ffma2(d0, q10, wP[0][1][0]);
        wP[0][1][1] = ffma2(d0, q11, wP[0][1][1]);
        wP[1][0][0] = ffma2(d1, q00, wP[1][0][0]);
        wP[1][0][1] = ffma2(d1, q01, wP[1][0][1]);
        wP[1][1][0] = ffma2(d1, q10, wP[1][1][0]);
        wP[1][1][1] = ffma2(d1, q11, wP[1][1][1]);
        wP[2][0][0] = ffma2(d2, q00, wP[2][0][0]);
        wP[2][0][1] = ffma2(d2, q01, wP[2][0][1]);
        wP[2][1][0] = ffma2(d2, q10, wP[2][1][0]);
        wP[2][1][1] = ffma2(d2, q11, wP[2][1][1]);
        wP[3][0][0] = ffma2(d3, q00, wP[3][0][0]);
        wP[3][0][1] = ffma2(d3, q01, wP[3][0][1]);
        wP[3][1][0] = ffma2(d3, q10, wP[3][1][0]);
        wP[3][1][1] = ffma2(d3, q11, wP[3][1][1]);
    }

    // ---- apply ----
#pragma unroll
    for (int g = 0; g < 2; g++) {
        const int v0 = eh * 8 + g * 4;
#pragma unroll
        for (int j = 0; j < 4; j++) {
#pragma unroll
            for (int o = 0; o < DOUT; o++) {
                float4 tf = *(const float4*)(tmp_w + j * TMP_ESTR + o * 16 + v0);
                u64 t01 = pack2(tf.x, tf.y), t23 = pack2(tf.z, tf.w);
                acc[j][o] = ffma2(wP[j][g][0], t01, acc[j][o]);
                acc[j][o] = ffma2(wP[j][g][1], t23, acc[j][o]);
            }
        }
    }
}

// ---------------------------------------------------------------------------
__global__ void __launch_bounds__(THREADS, 2)
conv_kernel(const float* __restrict__ features,
            const float* __restrict__ Ys,
            const float* __restrict__ radii,
            const float* __restrict__ n_norm,
            const int*   __restrict__ map_a,
            const int*   __restrict__ map_b,
            float* __restrict__ out)
{
    extern __shared__ __align__(16) float smem[];
    float* Rt    = smem + OFF_RT;      // [4][RBUF] ring (pair-slotted)
    float* tmp_s = smem + OFF_TMP;
    float* Ys_p  = smem + OFF_YS;
    float* radS  = smem + OFF_RAD;

    const int tid  = threadIdx.x;
    const int warp = tid >> 5;
    const int lane = tid & 31;
    const int m    = lane & 15;
    const int eh   = lane >> 4;
    const int e0   = blockIdx.x * TILE_E;
    const int leA  = eh * 2;
    const int lA   = warp * 4 + leA;
    const int lB   = lA + 1;
    float* tmp_w   = tmp_s + warp * TMP_WARP;
    const float* radS_w = radS + warp * RADS_WARP;

    const uint32_t rt_sm = (uint32_t)__cvta_generic_to_shared(Rt);

    // stage a path PAIR (paths PF, PF+1 -> contiguous buffer slots) via .cg
    // (L2-only: R never allocates in L1, leaving L1 for the features gather)
#define ISSUE_PAIR(PF)                                                         \
    do {                                                                       \
        uint32_t base = rt_sm + (uint32_t)((((PF) >> 1) & 1) * 2 * RBUF * 4);  \
        const float* src0 = R_pad + (size_t)(PF) * RBUF;                       \
        _Pragma("unroll")                                                      \
        for (int c = tid; c < 2 * RBUF / 4; c += THREADS) {                    \
            asm volatile("cp.async.cg.shared.global [%0], [%1], 16;"           \
                         :: "r"(base + (uint32_t)(c * 16)), "l"(src0 + c * 4));\
        }                                                                      \
        asm volatile("cp.async.commit_group;" ::: "memory");                   \
    } while (0)

#define ISSUE_ONE(P)                                                           \
    do {                                                                       \
        uint32_t base = rt_sm + (uint32_t)(((P) & 3) * RBUF * 4);              \
        const float* src0 = R_pad + (size_t)(P) * RBUF;                        \
        _Pragma("unroll")                                                      \
        for (int c = tid; c < RBUF / 4; c += THREADS) {                        \
            asm volatile("cp.async.cg.shared.global [%0], [%1], 16;"           \
                         :: "r"(base + (uint32_t)(c * 16)), "l"(src0 + c * 4));\
        }                                                                      \
        asm volatile("cp.async.commit_group;" ::: "memory");                   \
    } while (0)

    ISSUE_PAIR(0);   // latency hidden behind the prologue below

    // ---- stage padded Ys ----
    for (int idx = tid; idx < TILE_E * 25; idx += THREADS) {
        int le = idx / 25, f = idx - le * 25;
        int e  = e0 + le;
        int off = (f < 1) ? f : (f < 4) ? 3 + f : (f < 9) ? 8 + f
                : (f < 16) ? 11 + f : 12 + f;
        Ys_p[le * YS_STR + off] = (e < N_EDGES) ? Ys[(size_t)e * 25 + f] : 0.f;
    }

    // ---- per-warp duplicated radial table ----
    for (int idx = lane; idx < RADS_WARP; idx += 32) {
        int r = idx >> 3, j = (idx & 7) >> 1;
        int e = e0 + warp * 4 + j;
        bool v = (e < N_EDGES);
        radS[warp * RADS_WARP + idx] =
            v ? radii[(size_t)(v ? e : 0) * N_RBF + r] : 0.f;
    }

    // ---- per-lane bindings ----
    const int eA = e0 + lA, eB = e0 + lB;
    const bool vA = (eA < N_EDGES), vB = (eB < N_EDGES);
    const int eAc = vA ? eA : 0, eBc = vB ? eB : 0;

    u64 FAB[9];
    {
        const float* fA = features + (size_t)map_b[eAc] * FEAT;
        const float* fB = features + (size_t)map_b[eBc] * FEAT;
        FAB[0] = pack2(fA[m], fB[m]);
#pragma unroll
        for (int i = 0; i < 3; i++)
            FAB[1 + i] = pack2(fA[16 + m * 3 + i], fB[16 + m * 3 + i]);
#pragma unroll
        for (int i = 0; i < 5; i++)
            FAB[4 + i] = pack2(fA[64 + m * 5 + i], fB[64 + m * 5 + i]);
    }

    const int   aA  = map_a[eAc];
    const int   aB  = map_a[eBc];
    const float nnA = vA ? n_norm[aA] : 0.f;
    const float nnB = vB ? n_norm[aB] : 0.f;

    u64 acc[4][5];
#pragma unroll
    for (int j = 0; j < 4; j++)
#pragma unroll
        for (int o = 0; o < 5; o++) acc[j][o] = 0ull;

    // PAIR_SYNC(k): pair k's staging was issued at sync k-1 (~1 pair-compute of
    // slack). Drain it, barrier (frees pair k-1's slots == pair k+1's slots),
    // then issue pair k+1. One barrier per TWO paths.
#define PAIR_SYNC(K)                                                           \
    do {                                                                       \
        asm volatile("cp.async.wait_group 0;" ::: "memory");                   \
        __syncthreads();                                                       \
        if ((K) < 8)      ISSUE_PAIR(2 * (K) + 2);                             \
        else if ((K) == 8) ISSUE_ONE(18);                                      \
    } while (0)

#define DO(P, IO, II, LF, CGOFF)                                               \
    do_path<IO, II, LF, CGOFF>(FAB, Ys_p, Rt + ((P) & 3) * RBUF,               \
                               tmp_w, radS_w, m, eh, lA, lB, leA, acc)

#define EMIT(DOUT, EXPR_IDX)                                                   \
    do {                                                                       \
        float tot[4][DOUT];                                                    \
        _Pragma("unroll")                                                      \
        for (int j = 0; j < 4; j++)                                            \
            _Pragma("unroll")                                                  \
            for (int o = 0; o < (DOUT); o++) {                                 \
                u64 s = fadd2(acc[j][o],                                       \
                              __shfl_xor_sync(0xffffffffu, acc[j][o], 16));    \
                float lo, hi; unpack2(s, lo, hi);                              \
                tot[j][o] = lo + hi;                                           \
            }                                                                  \
        _Pragma("unroll")                                                      \
        for (int o = 0; o < (DOUT); o++) {                                     \
            if (vA) atomicAdd(&out[(size_t)aA * FEAT + (EXPR_IDX)],            \
                              nnA * tot[leA][o]);                              \
            if (vB) atomicAdd(&out[(size_t)aB * FEAT + (EXPR_IDX)],            \
                              nnB * tot[leA + 1][o]);                          \
        }                                                                      \
    } while (0)

#define CLEAR()                                                                \
    do {                                                                       \
        _Pragma("unroll")                                                      \
        for (int j = 0; j < 4; j++)                                            \
            _Pragma("unroll")                                                  \
            for (int o = 0; o < 5; o++) acc[j][o] = 0ull;                      \
    } while (0)

    // pair 0: paths 0,1
    PAIR_SYNC(0);
    DO(0, 0, 0, 0, 0);
    DO(1, 0, 1, 1, 1);
    // pair 1: paths 2 (end io=0), 3
    PAIR_SYNC(1);
    DO(2, 0, 2, 2, 10);
    EMIT(1, m);
    CLEAR();
    DO(3, 1, 0, 1, 35);
    // pair 2: paths 4,5
    PAIR_SYNC(2);
    DO(4, 1, 1, 0, 44);
    DO(5, 1, 1, 1, 53);
    // pair 3: paths 6,7
    PAIR_SYNC(3);
    DO(6, 1, 1, 2, 80);
    DO(7, 1, 2, 1, 125);
    // pair 4: paths 8,9 (end io=1)
    PAIR_SYNC(4);
    DO(8, 1, 2, 2, 170);
    DO(9, 1, 2, 3, 245);
    EMIT(3, 16 + m * 3 + o);
    CLEAR();
    // pair 5: paths 10,11
    PAIR_SYNC(5);
    DO(10, 2, 0, 2, 350);
    DO(11, 2, 1, 1, 375);
    // pair 6: paths 12,13
    PAIR_SYNC(6);
    DO(12, 2, 1, 2, 420);
    DO(13, 2, 1, 3, 495);
    // pair 7: paths 14,15
    PAIR_SYNC(7);
    DO(14, 2, 2, 0, 600);
    DO(15, 2, 2, 1, 625);
    // pair 8: paths 16,17
    PAIR_SYNC(8);
    DO(16, 2, 2, 2, 700);
    DO(17, 2, 2, 3, 825);
    // pair 9: path 18 (end io=2)
    PAIR_SYNC(9);
    DO(18, 2, 2, 4, 1000);
    EMIT(5, 64 + m * 5 + o);

#undef PAIR_SYNC
#undef DO
#undef EMIT
#undef CLEAR
#undef ISSUE_PAIR
#undef ISSUE_ONE
}

// ---------------------------------------------------------------------------
extern "C" void kernel_launch(void* const* d_in, const int* in_sizes, int n_in,
                              void* d_out, int out_size)
{
    const float* features = (const float*)d_in[0];
    const float* R        = (const float*)d_in[1];
    const float* Ys       = (const float*)d_in[2];
    const float* radii    = (const float*)d_in[3];
    const float* cg       = (const float*)d_in[4];
    const float* n_norm   = (const float*)d_in[5];
    const int*   map_a    = (const int*)d_in[6];
    const int*   map_b    = (const int*)d_in[7];
    float*       out      = (float*)d_out;

    cudaFuncSetAttribute(conv_kernel,
                         cudaFuncAttributeMaxDynamicSharedMemorySize,
                         SMEM_BYTES);

    cudaMemcpyToSymbolAsync(cg_c, cg, 1225 * sizeof(float), 0,
                            cudaMemcpyDeviceToDevice, 0);
    cudaMemsetAsync(out, 0, (size_t)out_size * sizeof(float));

    prep_kernel<<<(NPATH * RBUF + 255) / 256, 256>>>(R);

    int grid = (N_EDGES + TILE_E - 1) / TILE_E;   // 7813
    conv_kernel<<<grid, THREADS, SMEM_BYTES>>>(features, Ys, radii, n_norm,
                                               map_a, map_b, out);
}

// round 14
// speedup vs baseline: 5.3766x; 3.0229x over previous
#include <cuda_runtime.h>
#include <cstdint>

#define N_EDGES 250000
#define N_RBF   10
#define FEAT    144
#define P_TOTAL 4864
#define TILE_E  32
#define THREADS 256
#define NWARP   (THREADS / 32)          // 8
#define VSTRIDE 20                      // Rt w-row stride (16 used + 4 pad)
#define RSLICE  (16 * VSTRIDE)          // 320 floats per r-slice
#define RBUF    (N_RBF * RSLICE)        // 3200 floats per path slice (800 chunks)
#define YS_STR  40                      // padded Ys per-edge stride
#define TMP_ESTR 88                     // tmp per-edge stride
#define TMP_WARP (4 * TMP_ESTR)         // 352 floats per warp
#define RADS_WARP 80                    // per-warp radial table
#define NPATH   19

typedef unsigned long long u64;

__constant__ float cg_c[1225];
__device__ float R_pad[NPATH * RBUF];   // padded+transposed+norm-folded R

// ---- packed f32x2 helpers -------------------------------------------------
__device__ __forceinline__ u64 pack2(float lo, float hi) {
    u64 r; asm("mov.b64 %0, {%1,%2};" : "=l"(r) : "f"(lo), "f"(hi)); return r;
}
__device__ __forceinline__ void unpack2(u64 v, float& lo, float& hi) {
    asm("mov.b64 {%0,%1}, %2;" : "=f"(lo), "=f"(hi) : "l"(v));
}
__device__ __forceinline__ u64 ffma2(u64 a, u64 b, u64 c) {
    u64 d; asm("fma.rn.f32x2 %0, %1, %2, %3;" : "=l"(d) : "l"(a), "l"(b), "l"(c));
    return d;
}
__device__ __forceinline__ u64 fmul2(u64 a, u64 b) {
    u64 d; asm("mul.rn.f32x2 %0, %1, %2;" : "=l"(d) : "l"(a), "l"(b)); return d;
}
__device__ __forceinline__ u64 fadd2(u64 a, u64 b) {
    u64 d; asm("add.rn.f32x2 %0, %1, %2;" : "=l"(d) : "l"(a), "l"(b)); return d;
}

// named-barrier helpers (count = all 256 threads)
__device__ __forceinline__ void bar_sync_n(int id) {
    asm volatile("bar.sync %0, 256;" :: "r"(id) : "memory");
}
__device__ __forceinline__ void bar_arrive_n(int id) {
    asm volatile("bar.arrive %0, 256;" :: "r"(id) : "memory");
}

// ---------------------------------------------------------------------------
__global__ void prep_kernel(const float* __restrict__ R)
{
    const float norms[NPATH] = {
        1.0f, 0.57735026918962576f, 0.44721359549995794f,
        0.57735026918962576f, 1.0f, 0.57735026918962576f,
        0.44721359549995794f, 0.57735026918962576f,
        0.44721359549995794f, 0.37796447300922723f,
        0.44721359549995794f, 0.57735026918962576f,
        0.44721359549995794f, 0.37796447300922723f, 1.0f,
        0.57735026918962576f, 0.44721359549995794f,
        0.37796447300922723f, 0.33333333333333333f
    };
    int idx = blockIdx.x * blockDim.x + threadIdx.x;
    if (idx >= NPATH * RBUF) return;
    int p    = idx / RBUF,   rem  = idx - p * RBUF;
    int r    = rem / RSLICE; int rem2 = rem - r * RSLICE;
    int w    = rem2 / VSTRIDE, v = rem2 - w * VSTRIDE;
    float val = 0.f;
    if (v < 16)
        val = R[(size_t)r * P_TOTAL + p * 256 + w * 16 + v] * norms[p];
    R_pad[idx] = val;
}

// ---------------------------------------------------------------------------
// tmp phase (R-independent): packed tmp[v=m][o] for the (A,B) pair ->
// published to per-warp scratch.
// ---------------------------------------------------------------------------
template<int IO, int II, int LF, int CGOFF>
__device__ __forceinline__ void tmp_phase(
    const u64 (&FAB)[9],
    const float* __restrict__ Ys_p,
    float* __restrict__ tmp_w,
    int m, int lA, int lB, int leA)
{
    constexpr int DOUT = 2 * IO + 1;
    constexpr int DI   = 2 * II + 1;
    constexpr int DF   = 2 * LF + 1;
    constexpr int FB0  = (II == 0) ? 0 : ((II == 1) ? 1 : 4);
    constexpr int YB   = (LF == 0) ? 0 : (LF == 1) ? 4 : (LF == 2) ? 12
                       : (LF == 3) ? 20 : 28;

    u64 yAB[DF];
    {
        float ya[DF], yb[DF];
        const float* pa = Ys_p + lA * YS_STR + YB;
        const float* pb = Ys_p + lB * YS_STR + YB;
#pragma unroll
        for (int f4 = 0; f4 < DF / 4; f4++) {
            float4 qa = *(const float4*)(pa + 4 * f4);
            float4 qb = *(const float4*)(pb + 4 * f4);
            ya[4*f4+0]=qa.x; ya[4*f4+1]=qa.y; ya[4*f4+2]=qa.z; ya[4*f4+3]=qa.w;
            yb[4*f4+0]=qb.x; yb[4*f4+1]=qb.y; yb[4*f4+2]=qb.z; yb[4*f4+3]=qb.w;
        }
#pragma unroll
        for (int f = (DF / 4) * 4; f < DF; f++) { ya[f] = pa[f]; yb[f] = pb[f]; }
#pragma unroll
        for (int f = 0; f < DF; f++) yAB[f] = pack2(ya[f], yb[f]);
    }

    u64 tAB[DOUT];
#pragma unroll
    for (int o = 0; o < DOUT; o++) tAB[o] = 0ull;

#pragma unroll
    for (int f = 0; f < DF; f++) {
#pragma unroll
        for (int o = 0; o < DOUT; o++) {
            float c0 = cg_c[CGOFF + (o * DI + 0) * DF + f];
            u64 g = fmul2(FAB[FB0], pack2(c0, c0));
#pragma unroll
            for (int i = 1; i < DI; i++) {
                float c = cg_c[CGOFF + (o * DI + i) * DF + f];
                g = ffma2(FAB[FB0 + i], pack2(c, c), g);
            }
            tAB[o] = ffma2(yAB[f], g, tAB[o]);
        }
    }

    __syncwarp();
#pragma unroll
    for (int o = 0; o < DOUT; o++) {
        float lo, hi; unpack2(tAB[o], lo, hi);
        tmp_w[ leA      * TMP_ESTR + o * 16 + m] = lo;
        tmp_w[(leA + 1) * TMP_ESTR + o * 16 + m] = hi;
    }
    __syncwarp();
}

// ---------------------------------------------------------------------------
// W + apply phase (reads Rt from smem ring; r-outer, radS loads hoisted).
// ---------------------------------------------------------------------------
template<int IO>
__device__ __forceinline__ void w_phase(
    const float* __restrict__ Rt,
    const float* __restrict__ tmp_w,
    const float* __restrict__ radS_w,
    int m, int eh,
    u64 (&acc)[4][5])
{
    constexpr int DOUT = 2 * IO + 1;

    const float* row = Rt + m * VSTRIDE + eh * 8;
    u64 wP[4][2][2];
#pragma unroll
    for (int j = 0; j < 4; j++)
#pragma unroll
        for (int g = 0; g < 2; g++) { wP[j][g][0] = 0ull; wP[j][g][1] = 0ull; }

#pragma unroll
    for (int r = 0; r < N_RBF; r++) {
        float4 rd0 = *(const float4*)(radS_w + r * 8);
        float4 rd1 = *(const float4*)(radS_w + r * 8 + 4);
        u64 d0 = pack2(rd0.x, rd0.y);
        u64 d1 = pack2(rd0.z, rd0.w);
        u64 d2 = pack2(rd1.x, rd1.y);
        u64 d3 = pack2(rd1.z, rd1.w);
        float4 q0 = *(const float4*)(row + r * RSLICE);
        float4 q1 = *(const float4*)(row + r * RSLICE + 4);
        u64 q00 = pack2(q0.x, q0.y), q01 = pack2(q0.z, q0.w);
        u64 q10 = pack2(q1.x, q1.y), q11 = pack2(q1.z, q1.w);
        wP[0][0][0] = ffma2(d0, q00, wP[0][0][0]);
        wP[0][0][1] = ffma2(d0, q01, wP[0][0][1]);
        wP[0][1][0] = ffma2(d0, q10, wP[0][1][0]);
        wP[0][1][1] = ffma2(d0, q11, wP[0][1][1]);
        wP[1][0][0] = ffma2(d1, q00, wP[1][0][0]);
        wP[1][0][1] = ffma2(d1, q01, wP[1][0][1]);
        wP[1][1][0] = ffma2(d1, q10, wP[1][1][0]);
        wP[1][1][1] = ffma2(d1, q11, wP[1][1][1]);
        wP[2][0][0] = ffma2(d2, q00, wP[2][0][0]);
        wP[2][0][1] = ffma2(d2, q01, wP[2][0][1]);
        wP[2][1][0] = ffma2(d2, q10, wP[2][1][0]);
        wP[2][1][1] = ffma2(d2, q11, wP[2][1][1]);
        wP[3][0][0] = ffma2(d3, q00, wP[3][0][0]);
        wP[3][0][1] = ffma2(d3, q01, wP[3][0][1]);
        wP[3][1][0] = ffma2(d3, q10, wP[3][1][0]);
        wP[3][1][1] = ffma2(d3, q11, wP[3][1][1]);
    }

#pragma unroll
    for (int g = 0; g < 2; g++) {
        const int v0 = eh * 8 + g * 4;
#pragma unroll
        for (int j = 0; j < 4; j++) {
#pragma unroll
            for (int o = 0; o < DOUT; o++) {
                float4 tf = *(const float4*)(tmp_w + j * TMP_ESTR + o * 16 + v0);
                u64 t01 = pack2(tf.x, tf.y), t23 = pack2(tf.z, tf.w);
                acc[j][o] = ffma2(wP[j][g][0], t01, acc[j][o]);
                acc[j][o] = ffma2(wP[j][g][1], t23, acc[j][o]);
            }
        }
    }
}

// ---------------------------------------------------------------------------
__global__ void __launch_bounds__(THREADS, 2)
conv_kernel(const float* __restrict__ features,
            const float* __restrict__ Ys,
            const float* __restrict__ radii,
            const float* __restrict__ n_norm,
            const int*   __restrict__ map_a,
            const int*   __restrict__ map_b,
            float* __restrict__ out)
{
    __shared__ __align__(16) float Rt[3][RBUF];           // 38.4 kB (as R8)
    __shared__ __align__(16) float tmp_s[NWARP * TMP_WARP];
    __shared__ __align__(16) float Ys_p[TILE_E * YS_STR];
    __shared__ __align__(16) float radS[NWARP * RADS_WARP];

    const int tid  = threadIdx.x;
    const int warp = tid >> 5;
    const int lane = tid & 31;
    const int m    = lane & 15;
    const int eh   = lane >> 4;
    const int e0   = blockIdx.x * TILE_E;
    const int leA  = eh * 2;
    const int lA   = warp * 4 + leA;
    const int lB   = lA + 1;
    float* tmp_w   = tmp_s + warp * TMP_WARP;
    const float* radS_w = radS + warp * RADS_WARP;

    const uint32_t rt_sm = (uint32_t)__cvta_generic_to_shared(&Rt[0][0]);

    // all-thread staging (prologue only): 800 16B chunks per path
#define ISSUE_ALL(P)                                                           \
    do {                                                                       \
        uint32_t base = rt_sm + (uint32_t)(((P) % 3) * (RBUF * 4));            \
        const float* src0 = R_pad + (size_t)(P) * RBUF;                        \
        for (int c = tid; c < RBUF / 4; c += THREADS) {                        \
            asm volatile("cp.async.ca.shared.global [%0], [%1], 16;"           \
                         :: "r"(base + (uint32_t)(c * 16)), "l"(src0 + c * 4));\
        }                                                                      \
        asm volatile("cp.async.commit_group;" ::: "memory");                   \
    } while (0)

    // warp-0-only staging (main loop): 25 chunks per lane = 800 total (FIXED)
#define ISSUE_W0(P)                                                            \
    do {                                                                       \
        uint32_t base = rt_sm + (uint32_t)(((P) % 3) * (RBUF * 4));            \
        const float* src0 = R_pad + (size_t)(P) * RBUF;                        \
        _Pragma("unroll")                                                      \
        for (int k = 0; k < 25; k++) {                                         \
            int c = k * 32 + lane;                                             \
            asm volatile("cp.async.ca.shared.global [%0], [%1], 16;"           \
                         :: "r"(base + (uint32_t)(c * 16)), "l"(src0 + c * 4));\
        }                                                                      \
        asm volatile("cp.async.commit_group;" ::: "memory");                   \
    } while (0)

    ISSUE_ALL(0);
    ISSUE_ALL(1);

    // ---- stage padded Ys ----
    for (int idx = tid; idx < TILE_E * 25; idx += THREADS) {
        int le = idx / 25, f = idx - le * 25;
        int e  = e0 + le;
        int off = (f < 1) ? f : (f < 4) ? 3 + f : (f < 9) ? 8 + f
                : (f < 16) ? 11 + f : 12 + f;
        Ys_p[le * YS_STR + off] = (e < N_EDGES) ? Ys[(size_t)e * 25 + f] : 0.f;
    }

    // ---- per-warp duplicated radial table ----
    for (int idx = lane; idx < RADS_WARP; idx += 32) {
        int r = idx >> 3, j = (idx & 7) >> 1;
        int e = e0 + warp * 4 + j;
        bool v = (e < N_EDGES);
        radS[warp * RADS_WARP + idx] =
            v ? radii[(size_t)(v ? e : 0) * N_RBF + r] : 0.f;
    }

    // ---- per-lane bindings ----
    const int eA = e0 + lA, eB = e0 + lB;
    const bool vA = (eA < N_EDGES), vB = (eB < N_EDGES);
    const int eAc = vA ? eA : 0, eBc = vB ? eB : 0;

    u64 FAB[9];
    {
        const float* fA = features + (size_t)map_b[eAc] * FEAT;
        const float* fB = features + (size_t)map_b[eBc] * FEAT;
        FAB[0] = pack2(fA[m], fB[m]);
#pragma unroll
        for (int i = 0; i < 3; i++)
            FAB[1 + i] = pack2(fA[16 + m * 3 + i], fB[16 + m * 3 + i]);
#pragma unroll
        for (int i = 0; i < 5; i++)
            FAB[4 + i] = pack2(fA[64 + m * 5 + i], fB[64 + m * 5 + i]);
    }

    const int   aA  = map_a[eAc];
    const int   aB  = map_a[eBc];
    const float nnA = vA ? n_norm[aA] : 0.f;
    const float nnB = vB ? n_norm[aB] : 0.f;

    u64 acc[4][5];
#pragma unroll
    for (int j = 0; j < 4; j++)
#pragma unroll
        for (int o = 0; o < 5; o++) acc[j][o] = 0ull;

    // prologue barrier: paths 0,1 staged+visible, Ys_p/radS visible.
    asm volatile("cp.async.wait_group 0;" ::: "memory");
    __syncthreads();

    // Named-barrier producer/consumer pipeline. FULL[b] = id 1+b,
    // EMPTY[b] = id 4+b (b = P%3). Count = 256 everywhere.
    // Warp 0: (backpressure) sync EMPTY[(P+2)%3] for P>=1, stage P+2,
    //         tmp(P), drain own cp.async FIFO to path P, membar,
    //         arrive FULL[P%3] (P>=2; paths 0,1 covered by prologue).
    // Warps 1-7: tmp(P) freely, sync FULL[P%3] (P>=2), W(P),
    //            arrive EMPTY[P%3].
#define STEP(P, IO, II, LF, CGOFF)                                             \
    do {                                                                       \
        if (warp == 0) {                                                       \
            if ((P) >= 1 && (P) <= 16) bar_sync_n(4 + (((P) + 2) % 3));        \
            if ((P) <= 16) ISSUE_W0((P) + 2);                                  \
        }                                                                      \
        tmp_phase<IO, II, LF, CGOFF>(FAB, Ys_p, tmp_w, m, lA, lB, leA);        \
        if (warp == 0) {                                                       \
            if ((P) <= 16)                                                     \
                asm volatile("cp.async.wait_group 2;" ::: "memory");           \
            else if ((P) == 17)                                                \
                asm volatile("cp.async.wait_group 1;" ::: "memory");           \
            else                                                               \
                asm volatile("cp.async.wait_group 0;" ::: "memory");           \
            if ((P) >= 2) {                                                    \
                asm volatile("membar.cta;" ::: "memory");                      \
                bar_arrive_n(1 + ((P) % 3));                                   \
            }                                                                  \
        } else {                                                               \
            if ((P) >= 2) bar_sync_n(1 + ((P) % 3));                           \
        }                                                                      \
        w_phase<IO>(Rt[(P) % 3], tmp_w, radS_w, m, eh, acc);                   \
        if (warp != 0) bar_arrive_n(4 + ((P) % 3));                            \
    } while (0)

#define EMIT(DOUT, EXPR_IDX)                                                   \
    do {                                                                       \
        float tot[4][DOUT];                                                    \
        _Pragma("unroll")                                                      \
        for (int j = 0; j < 4; j++)                                            \
            _Pragma("unroll")                                                  \
            for (int o = 0; o < (DOUT); o++) {                                 \
                u64 s = fadd2(acc[j][o],                                       \
                              __shfl_xor_sync(0xffffffffu, acc[j][o], 16));    \
                float lo, hi; unpack2(s, lo, hi);                              \
                tot[j][o] = lo + hi;                                           \
            }                                                                  \
        _Pragma("unroll")                                                      \
        for (int o = 0; o < (DOUT); o++) {                                     \
            if (vA) atomicAdd(&out[(size_t)aA * FEAT + (EXPR_IDX)],            \
                              nnA * tot[leA][o]);                              \
            if (vB) atomicAdd(&out[(size_t)aB * FEAT + (EXPR_IDX)],            \
                              nnB * tot[leA + 1][o]);                          \
        }                                                                      \
    } while (0)

#define CLEAR()                                                                \
    do {                                                                       \
        _Pragma("unroll")                                                      \
        for (int j = 0; j < 4; j++)                                            \
            _Pragma("unroll")                                                  \
            for (int o = 0; o < 5; o++) acc[j][o] = 0ull;                      \
    } while (0)

    // ---------------- io = 0 (DOUT = 1, out offset 0) -----------------------
    STEP(0, 0, 0, 0, 0);
    STEP(1, 0, 1, 1, 1);
    STEP(2, 0, 2, 2, 10);
    EMIT(1, m);
    CLEAR();

    // ---------------- io = 1 (DOUT = 3, out offset 16) ----------------------
    STEP(3, 1, 0, 1, 35);
    STEP(4, 1, 1, 0, 44);
    STEP(5, 1, 1, 1, 53);
    STEP(6, 1, 1, 2, 80);
    STEP(7, 1, 2, 1, 125);
    STEP(8, 1, 2, 2, 170);
    STEP(9, 1, 2, 3, 245);
    EMIT(3, 16 + m * 3 + o);
    CLEAR();

    // ---------------- io = 2 (DOUT = 5, out offset 64) ----------------------
    STEP(10, 2, 0, 2, 350);
    STEP(11, 2, 1, 1, 375);
    STEP(12, 2, 1, 2, 420);
    STEP(13, 2, 1, 3, 495);
    STEP(14, 2, 2, 0, 600);
    STEP(15, 2, 2, 1, 625);
    STEP(16, 2, 2, 2, 700);
    STEP(17, 2, 2, 3, 825);
    STEP(18, 2, 2, 4, 1000);
    EMIT(5, 64 + m * 5 + o);

#undef STEP
#undef EMIT
#undef CLEAR
#undef ISSUE_ALL
#undef ISSUE_W0
}

// ---------------------------------------------------------------------------
extern "C" void kernel_launch(void* const* d_in, const int* in_sizes, int n_in,
                              void* d_out, int out_size)
{
    const float* features = (const float*)d_in[0];
    const float* R        = (const float*)d_in[1];
    const float* Ys       = (const float*)d_in[2];
    const float* radii    = (const float*)d_in[3];
    const float* cg       = (const float*)d_in[4];
    const float* n_norm   = (const float*)d_in[5];
    const int*   map_a    = (const int*)d_in[6];
    const int*   map_b    = (const int*)d_in[7];
    float*       out      = (float*)d_out;

    cudaMemcpyToSymbolAsync(cg_c, cg, 1225 * sizeof(float), 0,
                            cudaMemcpyDeviceToDevice, 0);
    cudaMemsetAsync(out, 0, (size_t)out_size * sizeof(float));

    prep_kernel<<<(NPATH * RBUF + 255) / 256, 256>>>(R);

    int grid = (N_EDGES + TILE_E - 1) / TILE_E;   // 7813
    conv_kernel<<<grid, THREADS>>>(features, Ys, radii, n_norm,
                                   map_a, map_b, out);
}

// round 15
// speedup vs baseline: 5.5657x; 1.0352x over previous
#include <cuda_runtime.h>
#include <cstdint>

#define N_EDGES 250000
#define N_RBF   10
#define FEAT    144
#define P_TOTAL 4864
#define TILE_E  32
#define THREADS 256
#define NWARP   (THREADS / 32)          // 8
#define VSTRIDE 20                      // Rt w-row stride (16 used + 4 pad)
#define RSLICE  (16 * VSTRIDE)          // 320 floats per r-slice
#define RBUF    (N_RBF * RSLICE)        // 3200 floats per path slice
#define YS_STR  40                      // padded Ys per-edge stride
#define TMP_ESTR 88                     // tmp per-edge stride
#define TMP_WARP (4 * TMP_ESTR)         // 352 floats per warp
#define RADS_WARP 80                    // per-warp radial table
#define NPATH   19

typedef unsigned long long u64;

__constant__ float cg_c[1225];
__device__ float R_pad[NPATH * RBUF];   // padded+transposed+norm-folded R

// ---- packed f32x2 helpers -------------------------------------------------
__device__ __forceinline__ u64 pack2(float lo, float hi) {
    u64 r; asm("mov.b64 %0, {%1,%2};" : "=l"(r) : "f"(lo), "f"(hi)); return r;
}
__device__ __forceinline__ void unpack2(u64 v, float& lo, float& hi) {
    asm("mov.b64 {%0,%1}, %2;" : "=f"(lo), "=f"(hi) : "l"(v));
}
__device__ __forceinline__ u64 ffma2(u64 a, u64 b, u64 c) {
    u64 d; asm("fma.rn.f32x2 %0, %1, %2, %3;" : "=l"(d) : "l"(a), "l"(b), "l"(c));
    return d;
}
__device__ __forceinline__ u64 fmul2(u64 a, u64 b) {
    u64 d; asm("mul.rn.f32x2 %0, %1, %2;" : "=l"(d) : "l"(a), "l"(b)); return d;
}
__device__ __forceinline__ u64 fadd2(u64 a, u64 b) {
    u64 d; asm("add.rn.f32x2 %0, %1, %2;" : "=l"(d) : "l"(a), "l"(b)); return d;
}

// ---------------------------------------------------------------------------
__global__ void prep_kernel(const float* __restrict__ R)
{
    const float norms[NPATH] = {
        1.0f, 0.57735026918962576f, 0.44721359549995794f,
        0.57735026918962576f, 1.0f, 0.57735026918962576f,
        0.44721359549995794f, 0.57735026918962576f,
        0.44721359549995794f, 0.37796447300922723f,
        0.44721359549995794f, 0.57735026918962576f,
        0.44721359549995794f, 0.37796447300922723f, 1.0f,
        0.57735026918962576f, 0.44721359549995794f,
        0.37796447300922723f, 0.33333333333333333f
    };
    int idx = blockIdx.x * blockDim.x + threadIdx.x;
    if (idx >= NPATH * RBUF) return;
    int p    = idx / RBUF,   rem  = idx - p * RBUF;
    int r    = rem / RSLICE; int rem2 = rem - r * RSLICE;
    int w    = rem2 / VSTRIDE, v = rem2 - w * VSTRIDE;
    float val = 0.f;
    if (v < 16)
        val = R[(size_t)r * P_TOTAL + p * 256 + w * 16 + v] * norms[p];
    R_pad[idx] = val;
}

// ---------------------------------------------------------------------------
// tmp phase (R-independent): packed tmp[v=m][o] for the (A,B) pair ->
// published to per-warp scratch. Runs BEFORE the per-path barrier.
// ---------------------------------------------------------------------------
template<int IO, int II, int LF, int CGOFF>
__device__ __forceinline__ void tmp_phase(
    const u64 (&FAB)[9],
    const float* __restrict__ Ys_p,
    float* __restrict__ tmp_w,
    int m, int lA, int lB, int leA)
{
    constexpr int DOUT = 2 * IO + 1;
    constexpr int DI   = 2 * II + 1;
    constexpr int DF   = 2 * LF + 1;
    constexpr int FB0  = (II == 0) ? 0 : ((II == 1) ? 1 : 4);
    constexpr int YB   = (LF == 0) ? 0 : (LF == 1) ? 4 : (LF == 2) ? 12
                       : (LF == 3) ? 20 : 28;

    u64 yAB[DF];
    {
        float ya[DF], yb[DF];
        const float* pa = Ys_p + lA * YS_STR + YB;
        const float* pb = Ys_p + lB * YS_STR + YB;
#pragma unroll
        for (int f4 = 0; f4 < DF / 4; f4++) {
            float4 qa = *(const float4*)(pa + 4 * f4);
            float4 qb = *(const float4*)(pb + 4 * f4);
            ya[4*f4+0]=qa.x; ya[4*f4+1]=qa.y; ya[4*f4+2]=qa.z; ya[4*f4+3]=qa.w;
            yb[4*f4+0]=qb.x; yb[4*f4+1]=qb.y; yb[4*f4+2]=qb.z; yb[4*f4+3]=qb.w;
        }
#pragma unroll
        for (int f = (DF / 4) * 4; f < DF; f++) { ya[f] = pa[f]; yb[f] = pb[f]; }
#pragma unroll
        for (int f = 0; f < DF; f++) yAB[f] = pack2(ya[f], yb[f]);
    }

    u64 tAB[DOUT];
#pragma unroll
    for (int o = 0; o < DOUT; o++) tAB[o] = 0ull;

#pragma unroll
    for (int f = 0; f < DF; f++) {
#pragma unroll
        for (int o = 0; o < DOUT; o++) {
            float c0 = cg_c[CGOFF + (o * DI + 0) * DF + f];
            u64 g = fmul2(FAB[FB0], pack2(c0, c0));
#pragma unroll
            for (int i = 1; i < DI; i++) {
                float c = cg_c[CGOFF + (o * DI + i) * DF + f];
                g = ffma2(FAB[FB0 + i], pack2(c, c), g);
            }
            tAB[o] = ffma2(yAB[f], g, tAB[o]);
        }
    }

    __syncwarp();
#pragma unroll
    for (int o = 0; o < DOUT; o++) {
        float lo, hi; unpack2(tAB[o], lo, hi);
        tmp_w[ leA      * TMP_ESTR + o * 16 + m] = lo;
        tmp_w[(leA + 1) * TMP_ESTR + o * 16 + m] = hi;
    }
    __syncwarp();
}

// ---------------------------------------------------------------------------
// W + apply phase (reads Rt from smem ring; r-outer, radS loads hoisted).
// ---------------------------------------------------------------------------
template<int IO>
__device__ __forceinline__ void w_phase(
    const float* __restrict__ Rt,
    const float* __restrict__ tmp_w,
    const float* __restrict__ radS_w,
    int m, int eh,
    u64 (&acc)[4][5])
{
    constexpr int DOUT = 2 * IO + 1;

    const float* row = Rt + m * VSTRIDE + eh * 8;
    u64 wP[4][2][2];
#pragma unroll
    for (int j = 0; j < 4; j++)
#pragma unroll
        for (int g = 0; g < 2; g++) { wP[j][g][0] = 0ull; wP[j][g][1] = 0ull; }

#pragma unroll
    for (int r = 0; r < N_RBF; r++) {
        float4 rd0 = *(const float4*)(radS_w + r * 8);
        float4 rd1 = *(const float4*)(radS_w + r * 8 + 4);
        u64 d0 = pack2(rd0.x, rd0.y);
        u64 d1 = pack2(rd0.z, rd0.w);
        u64 d2 = pack2(rd1.x, rd1.y);
        u64 d3 = pack2(rd1.z, rd1.w);
        float4 q0 = *(const float4*)(row + r * RSLICE);
        float4 q1 = *(const float4*)(row + r * RSLICE + 4);
        u64 q00 = pack2(q0.x, q0.y), q01 = pack2(q0.z, q0.w);
        u64 q10 = pack2(q1.x, q1.y), q11 = pack2(q1.z, q1.w);
        wP[0][0][0] = ffma2(d0, q00, wP[0][0][0]);
        wP[0][0][1] = ffma2(d0, q01, wP[0][0][1]);
        wP[0][1][0] = ffma2(d0, q10, wP[0][1][0]);
        wP[0][1][1] = ffma2(d0, q11, wP[0][1][1]);
        wP[1][0][0] = ffma2(d1, q00, wP[1][0][0]);
        wP[1][0][1] = ffma2(d1, q01, wP[1][0][1]);
        wP[1][1][0] = ffma2(d1, q10, wP[1][1][0]);
        wP[1][1][1] = ffma2(d1, q11, wP[1][1][1]);
        wP[2][0][0] = ffma2(d2, q00, wP[2][0][0]);
        wP[2][0][1] = ffma2(d2, q01, wP[2][0][1]);
        wP[2][1][0] = ffma2(d2, q10, wP[2][1][0]);
        wP[2][1][1] = ffma2(d2, q11, wP[2][1][1]);
        wP[3][0][0] = ffma2(d3, q00, wP[3][0][0]);
        wP[3][0][1] = ffma2(d3, q01, wP[3][0][1]);
        wP[3][1][0] = ffma2(d3, q10, wP[3][1][0]);
        wP[3][1][1] = ffma2(d3, q11, wP[3][1][1]);
    }

#pragma unroll
    for (int g = 0; g < 2; g++) {
        const int v0 = eh * 8 + g * 4;
#pragma unroll
        for (int j = 0; j < 4; j++) {
#pragma unroll
            for (int o = 0; o < DOUT; o++) {
                float4 tf = *(const float4*)(tmp_w + j * TMP_ESTR + o * 16 + v0);
                u64 t01 = pack2(tf.x, tf.y), t23 = pack2(tf.z, tf.w);
                acc[j][o] = ffma2(wP[j][g][0], t01, acc[j][o]);
                acc[j][o] = ffma2(wP[j][g][1], t23, acc[j][o]);
            }
        }
    }
}

// ---------------------------------------------------------------------------
__global__ void __launch_bounds__(THREADS, 2)
conv_kernel(const float* __restrict__ features,
            const float* __restrict__ Ys,
            const float* __restrict__ radii,
            const float* __restrict__ n_norm,
            const int*   __restrict__ map_a,
            const int*   __restrict__ map_b,
            float* __restrict__ out)
{
    __shared__ __align__(16) float Rt[3][RBUF];           // 38.4 kB (R8 config)
    __shared__ __align__(16) float tmp_s[NWARP * TMP_WARP];
    __shared__ __align__(16) float Ys_p[TILE_E * YS_STR];
    __shared__ __align__(16) float radS[NWARP * RADS_WARP];

    const int tid  = threadIdx.x;
    const int warp = tid >> 5;
    const int lane = tid & 31;
    const int m    = lane & 15;
    const int eh   = lane >> 4;
    const int e0   = blockIdx.x * TILE_E;
    const int leA  = eh * 2;
    const int lA   = warp * 4 + leA;
    const int lB   = lA + 1;
    float* tmp_w   = tmp_s + warp * TMP_WARP;
    const float* radS_w = radS + warp * RADS_WARP;

    const uint32_t rt_sm = (uint32_t)__cvta_generic_to_shared(&Rt[0][0]);

    // linear cp.async staging from pre-laid-out R_pad (800 x 16B per path)
#define ISSUE(P)                                                               \
    do {                                                                       \
        uint32_t base = rt_sm + (uint32_t)(((P) % 3) * (RBUF * 4));            \
        const float* src0 = R_pad + (size_t)(P) * RBUF;                        \
        _Pragma("unroll")                                                      \
        for (int c = tid; c < RBUF / 4; c += THREADS) {                        \
            asm volatile("cp.async.ca.shared.global [%0], [%1], 16;"           \
                         :: "r"(base + (uint32_t)(c * 16)), "l"(src0 + c * 4));\
        }                                                                      \
        asm volatile("cp.async.commit_group;" ::: "memory");                   \
    } while (0)

    ISSUE(0);
    ISSUE(1);

    // ---- stage padded Ys ----
    for (int idx = tid; idx < TILE_E * 25; idx += THREADS) {
        int le = idx / 25, f = idx - le * 25;
        int e  = e0 + le;
        int off = (f < 1) ? f : (f < 4) ? 3 + f : (f < 9) ? 8 + f
                : (f < 16) ? 11 + f : 12 + f;
        Ys_p[le * YS_STR + off] = (e < N_EDGES) ? Ys[(size_t)e * 25 + f] : 0.f;
    }

    // ---- per-warp duplicated radial table ----
    for (int idx = lane; idx < RADS_WARP; idx += 32) {
        int r = idx >> 3, j = (idx & 7) >> 1;
        int e = e0 + warp * 4 + j;
        bool v = (e < N_EDGES);
        radS[warp * RADS_WARP + idx] =
            v ? radii[(size_t)(v ? e : 0) * N_RBF + r] : 0.f;
    }

    // ---- per-lane bindings ----
    const int eA = e0 + lA, eB = e0 + lB;
    const bool vA = (eA < N_EDGES), vB = (eB < N_EDGES);
    const int eAc = vA ? eA : 0, eBc = vB ? eB : 0;

    u64 FAB[9];
    {
        const float* fA = features + (size_t)map_b[eAc] * FEAT;
        const float* fB = features + (size_t)map_b[eBc] * FEAT;
        FAB[0] = pack2(fA[m], fB[m]);
#pragma unroll
        for (int i = 0; i < 3; i++)
            FAB[1 + i] = pack2(fA[16 + m * 3 + i], fB[16 + m * 3 + i]);
#pragma unroll
        for (int i = 0; i < 5; i++)
            FAB[4 + i] = pack2(fA[64 + m * 5 + i], fB[64 + m * 5 + i]);
    }

    const int   aA  = map_a[eAc];
    const int   aB  = map_a[eBc];
    const float nnA = vA ? n_norm[aA] : 0.f;
    const float nnB = vB ? n_norm[aB] : 0.f;

    u64 acc[4][5];
#pragma unroll
    for (int j = 0; j < 4; j++)
#pragma unroll
        for (int o = 0; o < 5; o++) acc[j][o] = 0ull;

    __syncthreads();   // Ys_p, radS visible before tmp_phase(0)

    // STEP P (reordered vs R8): tmp(P) runs BEFORE the barrier — warps arrive
    // at the barrier having done ~40% of the path's FMA, absorbing skew and
    // cp.async latency. Then drain to Rt[P], sync (all warps done reading
    // Rt[(P+2)%3] from path P-1), issue P+2, run W(P).
#define STEP(P, IO, II, LF, CGOFF)                                             \
    do {                                                                       \
        tmp_phase<IO, II, LF, CGOFF>(FAB, Ys_p, tmp_w, m, lA, lB, leA);        \
        if ((P) < 18)                                                          \
            asm volatile("cp.async.wait_group 1;" ::: "memory");               \
        else                                                                   \
            asm volatile("cp.async.wait_group 0;" ::: "memory");               \
        __syncthreads();                                                       \
        if ((P) < 17) ISSUE((P) + 2);                                          \
        w_phase<IO>(Rt[(P) % 3], tmp_w, radS_w, m, eh, acc);                   \
    } while (0)

#define EMIT(DOUT, EXPR_IDX)                                                   \
    do {                                                                       \
        float tot[4][DOUT];                                                    \
        _Pragma("unroll")                                                      \
        for (int j = 0; j < 4; j++)                                            \
            _Pragma("unroll")                                                  \
            for (int o = 0; o < (DOUT); o++) {                                 \
                u64 s = fadd2(acc[j][o],                                       \
                              __shfl_xor_sync(0xffffffffu, acc[j][o], 16));    \
                float lo, hi; unpack2(s, lo, hi);                              \
                tot[j][o] = lo + hi;                                           \
            }                                                                  \
        _Pragma("unroll")                                                      \
        for (int o = 0; o < (DOUT); o++) {                                     \
            if (vA) atomicAdd(&out[(size_t)aA * FEAT + (EXPR_IDX)],            \
                              nnA * tot[leA][o]);                              \
            if (vB) atomicAdd(&out[(size_t)aB * FEAT + (EXPR_IDX)],            \
                              nnB * tot[leA + 1][o]);                          \
        }                                                                      \
    } while (0)

#define CLEAR()                                                                \
    do {                                                                       \
        _Pragma("unroll")                                                      \
        for (int j = 0; j < 4; j++)                                            \
            _Pragma("unroll")                                                  \
            for (int o = 0; o < 5; o++) acc[j][o] = 0ull;                      \
    } while (0)

    // ---------------- io = 0 (DOUT = 1, out offset 0) -----------------------
    STEP(0, 0, 0, 0, 0);
    STEP(1, 0, 1, 1, 1);
    STEP(2, 0, 2, 2, 10);
    EMIT(1, m);
    CLEAR();

    // ---------------- io = 1 (DOUT = 3, out offset 16) ----------------------
    STEP(3, 1, 0, 1, 35);
    STEP(4, 1, 1, 0, 44);
    STEP(5, 1, 1, 1, 53);
    STEP(6, 1, 1, 2, 80);
    STEP(7, 1, 2, 1, 125);
    STEP(8, 1, 2, 2, 170);
    STEP(9, 1, 2, 3, 245);
    EMIT(3, 16 + m * 3 + o);
    CLEAR();

    // ---------------- io = 2 (DOUT = 5, out offset 64) ----------------------
    STEP(10, 2, 0, 2, 350);
    STEP(11, 2, 1, 1, 375);
    STEP(12, 2, 1, 2, 420);
    STEP(13, 2, 1, 3, 495);
    STEP(14, 2, 2, 0, 600);
    STEP(15, 2, 2, 1, 625);
    STEP(16, 2, 2, 2, 700);
    STEP(17, 2, 2, 3, 825);
    STEP(18, 2, 2, 4, 1000);
    EMIT(5, 64 + m * 5 + o);

#undef STEP
#undef EMIT
#undef CLEAR
#undef ISSUE
}

// ---------------------------------------------------------------------------
extern "C" void kernel_launch(void* const* d_in, const int* in_sizes, int n_in,
                              void* d_out, int out_size)
{
    const float* features = (const float*)d_in[0];
    const float* R        = (const float*)d_in[1];
    const float* Ys       = (const float*)d_in[2];
    const float* radii    = (const float*)d_in[3];
    const float* cg       = (const float*)d_in[4];
    const float* n_norm   = (const float*)d_in[5];
    const int*   map_a    = (const int*)d_in[6];
    const int*   map_b    = (const int*)d_in[7];
    float*       out      = (float*)d_out;

    cudaMemcpyToSymbolAsync(cg_c, cg, 1225 * sizeof(float), 0,
                            cudaMemcpyDeviceToDevice, 0);
    cudaMemsetAsync(out, 0, (size_t)out_size * sizeof(float));

    prep_kernel<<<(NPATH * RBUF + 255) / 256, 256>>>(R);

    int grid = (N_EDGES + TILE_E - 1) / TILE_E;   // 7813
    conv_kernel<<<grid, THREADS>>>(features, Ys, radii, n_norm,
                                   map_a, map_b, out);
}

// round 16
// speedup vs baseline: 5.6193x; 1.0096x over previous
#include <cuda_runtime.h>
#include <cstdint>

#define N_EDGES 250000
#define N_RBF   10
#define FEAT    144
#define P_TOTAL 4864
#define TILE_E  32
#define THREADS 256
#define NWARP   (THREADS / 32)          // 8
#define VSTRIDE 20                      // Rt w-row stride (16 used + 4 pad)
#define RSLICE  (16 * VSTRIDE)          // 320 floats per r-slice
#define RBUF    (N_RBF * RSLICE)        // 3200 floats per path slice
#define RBYTES  (RBUF * 4)              // 12800 bytes per path slice
#define YS_STR  40                      // padded Ys per-edge stride
#define TMP_ESTR 88                     // tmp per-edge stride
#define TMP_WARP (4 * TMP_ESTR)         // 352 floats per warp
#define RADS_WARP 80                    // per-warp radial table
#define NPATH   19

typedef unsigned long long u64;

__constant__ float cg_c[1225];
__device__ float R_pad[NPATH * RBUF];   // padded+transposed+norm-folded R

// ---- packed f32x2 helpers -------------------------------------------------
__device__ __forceinline__ u64 pack2(float lo, float hi) {
    u64 r; asm("mov.b64 %0, {%1,%2};" : "=l"(r) : "f"(lo), "f"(hi)); return r;
}
__device__ __forceinline__ void unpack2(u64 v, float& lo, float& hi) {
    asm("mov.b64 {%0,%1}, %2;" : "=f"(lo), "=f"(hi) : "l"(v));
}
__device__ __forceinline__ u64 ffma2(u64 a, u64 b, u64 c) {
    u64 d; asm("fma.rn.f32x2 %0, %1, %2, %3;" : "=l"(d) : "l"(a), "l"(b), "l"(c));
    return d;
}
__device__ __forceinline__ u64 fmul2(u64 a, u64 b) {
    u64 d; asm("mul.rn.f32x2 %0, %1, %2;" : "=l"(d) : "l"(a), "l"(b)); return d;
}
__device__ __forceinline__ u64 fadd2(u64 a, u64 b) {
    u64 d; asm("add.rn.f32x2 %0, %1, %2;" : "=l"(d) : "l"(a), "l"(b)); return d;
}

// ---- mbarrier helpers -------------------------------------------------------
__device__ __forceinline__ void mbar_init(uint32_t addr, uint32_t count) {
    asm volatile("mbarrier.init.shared.b64 [%0], %1;" :: "r"(addr), "r"(count)
                 : "memory");
}
__device__ __forceinline__ void mbar_expect_tx(uint32_t addr, uint32_t bytes) {
    asm volatile("mbarrier.arrive.expect_tx.shared.b64 _, [%0], %1;"
                 :: "r"(addr), "r"(bytes) : "memory");
}
__device__ __forceinline__ void mbar_wait(uint32_t addr, uint32_t parity) {
    asm volatile(
        "{\n\t"
        ".reg .pred P1;\n\t"
        "WAIT_LOOP_%=:\n\t"
        "mbarrier.try_wait.parity.acquire.cta.shared::cta.b64 P1, [%0], %1, 0x989680;\n\t"
        "@P1 bra.uni WAIT_DONE_%=;\n\t"
        "bra.uni WAIT_LOOP_%=;\n\t"
        "WAIT_DONE_%=:\n\t"
        "}"
        :: "r"(addr), "r"(parity) : "memory");
}
__device__ __forceinline__ void tma_bulk_1d(uint32_t dst_smem, const void* src,
                                            uint32_t bytes, uint32_t mbar) {
    asm volatile(
        "cp.async.bulk.shared::cluster.global.mbarrier::complete_tx::bytes "
        "[%0], [%1], %2, [%3];"
        :: "r"(dst_smem), "l"(src), "r"(bytes), "r"(mbar) : "memory");
}

// ---------------------------------------------------------------------------
// Prep: relayout R into R_pad[p][r][w*VSTRIDE + v] with 1/sqrt(df) folded in.
// ---------------------------------------------------------------------------
__global__ void prep_kernel(const float* __restrict__ R)
{
    const float norms[NPATH] = {
        1.0f, 0.57735026918962576f, 0.44721359549995794f,
        0.57735026918962576f, 1.0f, 0.57735026918962576f,
        0.44721359549995794f, 0.57735026918962576f,
        0.44721359549995794f, 0.37796447300922723f,
        0.44721359549995794f, 0.57735026918962576f,
        0.44721359549995794f, 0.37796447300922723f, 1.0f,
        0.57735026918962576f, 0.44721359549995794f,
        0.37796447300922723f, 0.33333333333333333f
    };
    int idx = blockIdx.x * blockDim.x + threadIdx.x;
    if (idx >= NPATH * RBUF) return;
    int p    = idx / RBUF,   rem  = idx - p * RBUF;
    int r    = rem / RSLICE; int rem2 = rem - r * RSLICE;
    int w    = rem2 / VSTRIDE, v = rem2 - w * VSTRIDE;
    float val = 0.f;
    if (v < 16)
        val = R[(size_t)r * P_TOTAL + p * 256 + w * 16 + v] * norms[p];
    R_pad[idx] = val;
}

// ---------------------------------------------------------------------------
// One path, f32x2-packed (identical compute to R8 champion).
// ---------------------------------------------------------------------------
template<int IO, int II, int LF, int CGOFF>
__device__ __forceinline__ void do_path(
    const u64 (&FAB)[9],
    const float* __restrict__ Ys_p,
    const float* __restrict__ Rt,
    float* __restrict__ tmp_w,
    const float* __restrict__ radS_w,
    int m, int eh, int lA, int lB, int leA,
    u64 (&acc)[4][5])
{
    constexpr int DOUT = 2 * IO + 1;
    constexpr int DI   = 2 * II + 1;
    constexpr int DF   = 2 * LF + 1;
    constexpr int FB0  = (II == 0) ? 0 : ((II == 1) ? 1 : 4);
    constexpr int YB   = (LF == 0) ? 0 : (LF == 1) ? 4 : (LF == 2) ? 12
                       : (LF == 3) ? 20 : 28;

    // ---- packed Ys ----
    u64 yAB[DF];
    {
        float ya[DF], yb[DF];
        const float* pa = Ys_p + lA * YS_STR + YB;
        const float* pb = Ys_p + lB * YS_STR + YB;
#pragma unroll
        for (int f4 = 0; f4 < DF / 4; f4++) {
            float4 qa = *(const float4*)(pa + 4 * f4);
            float4 qb = *(const float4*)(pb + 4 * f4);
            ya[4*f4+0]=qa.x; ya[4*f4+1]=qa.y; ya[4*f4+2]=qa.z; ya[4*f4+3]=qa.w;
            yb[4*f4+0]=qb.x; yb[4*f4+1]=qb.y; yb[4*f4+2]=qb.z; yb[4*f4+3]=qb.w;
        }
#pragma unroll
        for (int f = (DF / 4) * 4; f < DF; f++) { ya[f] = pa[f]; yb[f] = pb[f]; }
#pragma unroll
        for (int f = 0; f < DF; f++) yAB[f] = pack2(ya[f], yb[f]);
    }

    // ---- packed tmp[v=m][o] for the (A,B) pair ----
    u64 tAB[DOUT];
#pragma unroll
    for (int o = 0; o < DOUT; o++) tAB[o] = 0ull;

#pragma unroll
    for (int f = 0; f < DF; f++) {
#pragma unroll
        for (int o = 0; o < DOUT; o++) {
            float c0 = cg_c[CGOFF + (o * DI + 0) * DF + f];
            u64 g = fmul2(FAB[FB0], pack2(c0, c0));
#pragma unroll
            for (int i = 1; i < DI; i++) {
                float c = cg_c[CGOFF + (o * DI + i) * DF + f];
                g = ffma2(FAB[FB0 + i], pack2(c, c), g);
            }
            tAB[o] = ffma2(yAB[f], g, tAB[o]);
        }
    }

    // ---- publish tmp scalars to warp scratch ----
    __syncwarp();
#pragma unroll
    for (int o = 0; o < DOUT; o++) {
        float lo, hi; unpack2(tAB[o], lo, hi);
        tmp_w[ leA      * TMP_ESTR + o * 16 + m] = lo;
        tmp_w[(leA + 1) * TMP_ESTR + o * 16 + m] = hi;
    }
    __syncwarp();

    // ---- W: r-outer, radS loads hoisted across both v-quads ----
    const float* row = Rt + m * VSTRIDE + eh * 8;
    u64 wP[4][2][2];
#pragma unroll
    for (int j = 0; j < 4; j++)
#pragma unroll
        for (int g = 0; g < 2; g++) { wP[j][g][0] = 0ull; wP[j][g][1] = 0ull; }

#pragma unroll
    for (int r = 0; r < N_RBF; r++) {
        float4 rd0 = *(const float4*)(radS_w + r * 8);
        float4 rd1 = *(const float4*)(radS_w + r * 8 + 4);
        u64 d0 = pack2(rd0.x, rd0.y);
        u64 d1 = pack2(rd0.z, rd0.w);
        u64 d2 = pack2(rd1.x, rd1.y);
        u64 d3 = pack2(rd1.z, rd1.w);
        float4 q0 = *(const float4*)(row + r * RSLICE);
        float4 q1 = *(const float4*)(row + r * RSLICE + 4);
        u64 q00 = pack2(q0.x, q0.y), q01 = pack2(q0.z, q0.w);
        u64 q10 = pack2(q1.x, q1.y), q11 = pack2(q1.z, q1.w);
        wP[0][0][0] = ffma2(d0, q00, wP[0][0][0]);
        wP[0][0][1] = ffma2(d0, q01, wP[0][0][1]);
        wP[0][1][0] = ffma2(d0, q10, wP[0][1][0]);
        wP[0][1][1] = ffma2(d0, q11, wP[0][1][1]);
        wP[1][0][0] = ffma2(d1, q00, wP[1][0][0]);
        wP[1][0][1] = ffma2(d1, q01, wP[1][0][1]);
        wP[1][1][0] = ffma2(d1, q10, wP[1][1][0]);
        wP[1][1][1] = ffma2(d1, q11, wP[1][1][1]);
        wP[2][0][0] = ffma2(d2, q00, wP[2][0][0]);
        wP[2][0][1] = ffma2(d2, q01, wP[2][0][1]);
        wP[2][1][0] = ffma2(d2, q10, wP[2][1][0]);
        wP[2][1][1] = ffma2(d2, q11, wP[2][1][1]);
        wP[3][0][0] = ffma2(d3, q00, wP[3][0][0]);
        wP[3][0][1] = ffma2(d3, q01, wP[3][0][1]);
        wP[3][1][0] = ffma2(d3, q10, wP[3][1][0]);
        wP[3][1][1] = ffma2(d3, q11, wP[3][1][1]);
    }

    // ---- apply ----
#pragma unroll
    for (int g = 0; g < 2; g++) {
        const int v0 = eh * 8 + g * 4;
#pragma unroll
        for (int j = 0; j < 4; j++) {
#pragma unroll
            for (int o = 0; o < DOUT; o++) {
                float4 tf = *(const float4*)(tmp_w + j * TMP_ESTR + o * 16 + v0);
                u64 t01 = pack2(tf.x, tf.y), t23 = pack2(tf.z, tf.w);
                acc[j][o] = ffma2(wP[j][g][0], t01, acc[j][o]);
                acc[j][o] = ffma2(wP[j][g][1], t23, acc[j][o]);
            }
        }
    }
}

// ---------------------------------------------------------------------------
__global__ void __launch_bounds__(THREADS, 2)
conv_kernel(const float* __restrict__ features,
            const float* __restrict__ Ys,
            const float* __restrict__ radii,
            const float* __restrict__ n_norm,
            const int*   __restrict__ map_a,
            const int*   __restrict__ map_b,
            float* __restrict__ out)
{
    __shared__ __align__(16) float Rt[3][RBUF];           // 38.4 kB (R8 config)
    __shared__ __align__(16) float tmp_s[NWARP * TMP_WARP];
    __shared__ __align__(16) float Ys_p[TILE_E * YS_STR];
    __shared__ __align__(16) float radS[NWARP * RADS_WARP];
    __shared__ __align__(8)  u64   mbar[3];               // ring mbarriers

    const int tid  = threadIdx.x;
    const int warp = tid >> 5;
    const int lane = tid & 31;
    const int m    = lane & 15;
    const int eh   = lane >> 4;
    const int e0   = blockIdx.x * TILE_E;
    const int leA  = eh * 2;
    const int lA   = warp * 4 + leA;
    const int lB   = lA + 1;
    float* tmp_w   = tmp_s + warp * TMP_WARP;
    const float* radS_w = radS + warp * RADS_WARP;

    const uint32_t rt_sm   = (uint32_t)__cvta_generic_to_shared(&Rt[0][0]);
    const uint32_t mbar_sm = (uint32_t)__cvta_generic_to_shared(&mbar[0]);

    // TMA bulk staging of one full path slice (12.8 kB), single thread.
#define TMA_ISSUE(P)                                                           \
    do {                                                                       \
        uint32_t mb = mbar_sm + (uint32_t)(((P) % 3) * 8);                     \
        mbar_expect_tx(mb, RBYTES);                                            \
        tma_bulk_1d(rt_sm + (uint32_t)(((P) % 3) * RBYTES),                    \
                    R_pad + (size_t)(P) * RBUF, RBYTES, mb);                   \
    } while (0)

    // ---- init mbarriers (count=1: tid0's expect_tx is the only arrival) ----
    if (tid == 0) {
        mbar_init(mbar_sm,      1);
        mbar_init(mbar_sm + 8,  1);
        mbar_init(mbar_sm + 16, 1);
    }
    __syncthreads();                 // init visible before any wait/arm
    if (tid == 0) { TMA_ISSUE(0); TMA_ISSUE(1); }

    // ---- stage padded Ys ----
    for (int idx = tid; idx < TILE_E * 25; idx += THREADS) {
        int le = idx / 25, f = idx - le * 25;
        int e  = e0 + le;
        int off = (f < 1) ? f : (f < 4) ? 3 + f : (f < 9) ? 8 + f
                : (f < 16) ? 11 + f : 12 + f;
        Ys_p[le * YS_STR + off] = (e < N_EDGES) ? Ys[(size_t)e * 25 + f] : 0.f;
    }

    // ---- per-warp duplicated radial table ----
    for (int idx = lane; idx < RADS_WARP; idx += 32) {
        int r = idx >> 3, j = (idx & 7) >> 1;
        int e = e0 + warp * 4 + j;
        bool v = (e < N_EDGES);
        radS[warp * RADS_WARP + idx] =
            v ? radii[(size_t)(v ? e : 0) * N_RBF + r] : 0.f;
    }

    // ---- per-lane bindings ----
    const int eA = e0 + lA, eB = e0 + lB;
    const bool vA = (eA < N_EDGES), vB = (eB < N_EDGES);
    const int eAc = vA ? eA : 0, eBc = vB ? eB : 0;

    u64 FAB[9];
    {
        const float* fA = features + (size_t)map_b[eAc] * FEAT;
        const float* fB = features + (size_t)map_b[eBc] * FEAT;
        FAB[0] = pack2(fA[m], fB[m]);
#pragma unroll
        for (int i = 0; i < 3; i++)
            FAB[1 + i] = pack2(fA[16 + m * 3 + i], fB[16 + m * 3 + i]);
#pragma unroll
        for (int i = 0; i < 5; i++)
            FAB[4 + i] = pack2(fA[64 + m * 5 + i], fB[64 + m * 5 + i]);
    }

    const int   aA  = map_a[eAc];
    const int   aB  = map_a[eBc];
    const float nnA = vA ? n_norm[aA] : 0.f;
    const float nnB = vB ? n_norm[aB] : 0.f;

    u64 acc[4][5];
#pragma unroll
    for (int j = 0; j < 4; j++)
#pragma unroll
        for (int o = 0; o < 5; o++) acc[j][o] = 0ull;

    __syncthreads();   // Ys_p, radS visible

    // STEP P: wait FULL(slot P%3, parity (P/3)&1) -> barrier (all warps done
    // reading slot (P+2)%3 from path P-1; also all saw that mbar's flip at
    // STEP(P-1), so re-arming is race-free) -> tid0 arms+issues path P+2 ->
    // compute path P.
#define STEP(P, IO, II, LF, CGOFF)                                             \
    do {                                                                       \
        mbar_wait(mbar_sm + (uint32_t)(((P) % 3) * 8), ((P) / 3) & 1);         \
        __syncthreads();                                                       \
        if ((P) < 17 && tid == 0) TMA_ISSUE((P) + 2);                          \
        do_path<IO, II, LF, CGOFF>(FAB, Ys_p, Rt[(P) % 3], tmp_w,              \
                                   radS_w, m, eh, lA, lB, leA, acc);           \
    } while (0)

#define EMIT(DOUT, EXPR_IDX)                                                   \
    do {                                                                       \
        float tot[4][DOUT];                                                    \
        _Pragma("unroll")                                                      \
        for (int j = 0; j < 4; j++)                                            \
            _Pragma("unroll")                                                  \
            for (int o = 0; o < (DOUT); o++) {                                 \
                u64 s = fadd2(acc[j][o],                                       \
                              __shfl_xor_sync(0xffffffffu, acc[j][o], 16));    \
                float lo, hi; unpack2(s, lo, hi);                              \
                tot[j][o] = lo + hi;                                           \
            }                                                                  \
        _Pragma("unroll")                                                      \
        for (int o = 0; o < (DOUT); o++) {                                     \
            if (vA) atomicAdd(&out[(size_t)aA * FEAT + (EXPR_IDX)],            \
                              nnA * tot[leA][o]);                              \
            if (vB) atomicAdd(&out[(size_t)aB * FEAT + (EXPR_IDX)],            \
                              nnB * tot[leA + 1][o]);                          \
        }                                                                      \
    } while (0)

#define CLEAR()                                                                \
    do {                                                                       \
        _Pragma("unroll")                                                      \
        for (int j = 0; j < 4; j++)                                            \
            _Pragma("unroll")                                                  \
            for (int o = 0; o < 5; o++) acc[j][o] = 0ull;                      \
    } while (0)

    // ---------------- io = 0 (DOUT = 1, out offset 0) -----------------------
    STEP(0, 0, 0, 0, 0);
    STEP(1, 0, 1, 1, 1);
    STEP(2, 0, 2, 2, 10);
    EMIT(1, m);
    CLEAR();

    // ---------------- io = 1 (DOUT = 3, out offset 16) ----------------------
    STEP(3, 1, 0, 1, 35);
    STEP(4, 1, 1, 0, 44);
    STEP(5, 1, 1, 1, 53);
    STEP(6, 1, 1, 2, 80);
    STEP(7, 1, 2, 1, 125);
    STEP(8, 1, 2, 2, 170);
    STEP(9, 1, 2, 3, 245);
    EMIT(3, 16 + m * 3 + o);
    CLEAR();

    // ---------------- io = 2 (DOUT = 5, out offset 64) ----------------------
    STEP(10, 2, 0, 2, 350);
    STEP(11, 2, 1, 1, 375);
    STEP(12, 2, 1, 2, 420);
    STEP(13, 2, 1, 3, 495);
    STEP(14, 2, 2, 0, 600);
    STEP(15, 2, 2, 1, 625);
    STEP(16, 2, 2, 2, 700);
    STEP(17, 2, 2, 3, 825);
    STEP(18, 2, 2, 4, 1000);
    EMIT(5, 64 + m * 5 + o);

#undef STEP
#undef EMIT
#undef CLEAR
#undef TMA_ISSUE
}

// ---------------------------------------------------------------------------
extern "C" void kernel_launch(void* const* d_in, const int* in_sizes, int n_in,
                              void* d_out, int out_size)
{
    const float* features = (const float*)d_in[0];
    const float* R        = (const float*)d_in[1];
    const float* Ys       = (const float*)d_in[2];
    const float* radii    = (const float*)d_in[3];
    const float* cg       = (const float*)d_in[4];
    const float* n_norm   = (const float*)d_in[5];
    const int*   map_a    = (const int*)d_in[6];
    const int*   map_b    = (const int*)d_in[7];
    float*       out      = (float*)d_out;

    cudaMemcpyToSymbolAsync(cg_c, cg, 1225 * sizeof(float), 0,
                            cudaMemcpyDeviceToDevice, 0);
    cudaMemsetAsync(out, 0, (size_t)out_size * sizeof(float));

    prep_kernel<<<(NPATH * RBUF + 255) / 256, 256>>>(R);

    int grid = (N_EDGES + TILE_E - 1) / TILE_E;   // 7813
    conv_kernel<<<grid, THREADS>>>(features, Ys, radii, n_norm,
                                   map_a, map_b, out);
}

// round 17
// speedup vs baseline: 5.9482x; 1.0585x over previous
#include <cuda_runtime.h>
#include <cstdint>

#define N_EDGES 250000
#define N_RBF   10
#define FEAT    144
#define P_TOTAL 4864
#define TILE_E  32
#define THREADS 256
#define NWARP   (THREADS / 32)          // 8
#define VSTRIDE 20                      // Rt w-row stride (16 used + 4 pad)
#define RSLICE  (16 * VSTRIDE)          // 320 floats per r-slice
#define RBUF    (N_RBF * RSLICE)        // 3200 floats per path slice
#define RBYTES  (RBUF * 4)              // 12800 bytes per path slice
#define YS_STR  40                      // padded Ys per-edge stride
#define TMP_ESTR 88                     // tmp per-edge stride
#define TMP_WARP (4 * TMP_ESTR)         // 352 floats per warp
#define RADS_WARP 40                    // per-warp radial table: [r][j], NON-dup
#define NPATH   19

typedef unsigned long long u64;

__constant__ float cg_c[1225];
__device__ float R_pad[NPATH * RBUF];   // padded+transposed+norm-folded R

// ---- packed f32x2 helpers -------------------------------------------------
__device__ __forceinline__ u64 pack2(float lo, float hi) {
    u64 r; asm("mov.b64 %0, {%1,%2};" : "=l"(r) : "f"(lo), "f"(hi)); return r;
}
__device__ __forceinline__ void unpack2(u64 v, float& lo, float& hi) {
    asm("mov.b64 {%0,%1}, %2;" : "=f"(lo), "=f"(hi) : "l"(v));
}
__device__ __forceinline__ u64 ffma2(u64 a, u64 b, u64 c) {
    u64 d; asm("fma.rn.f32x2 %0, %1, %2, %3;" : "=l"(d) : "l"(a), "l"(b), "l"(c));
    return d;
}
__device__ __forceinline__ u64 fmul2(u64 a, u64 b) {
    u64 d; asm("mul.rn.f32x2 %0, %1, %2;" : "=l"(d) : "l"(a), "l"(b)); return d;
}
__device__ __forceinline__ u64 fadd2(u64 a, u64 b) {
    u64 d; asm("add.rn.f32x2 %0, %1, %2;" : "=l"(d) : "l"(a), "l"(b)); return d;
}

// ---- mbarrier helpers -------------------------------------------------------
__device__ __forceinline__ void mbar_init(uint32_t addr, uint32_t count) {
    asm volatile("mbarrier.init.shared.b64 [%0], %1;" :: "r"(addr), "r"(count)
                 : "memory");
}
__device__ __forceinline__ void mbar_expect_tx(uint32_t addr, uint32_t bytes) {
    asm volatile("mbarrier.arrive.expect_tx.shared.b64 _, [%0], %1;"
                 :: "r"(addr), "r"(bytes) : "memory");
}
__device__ __forceinline__ void mbar_wait(uint32_t addr, uint32_t parity) {
    asm volatile(
        "{\n\t"
        ".reg .pred P1;\n\t"
        "WAIT_LOOP_%=:\n\t"
        "mbarrier.try_wait.parity.acquire.cta.shared::cta.b64 P1, [%0], %1, 0x989680;\n\t"
        "@P1 bra.uni WAIT_DONE_%=;\n\t"
        "bra.uni WAIT_LOOP_%=;\n\t"
        "WAIT_DONE_%=:\n\t"
        "}"
        :: "r"(addr), "r"(parity) : "memory");
}
__device__ __forceinline__ void tma_bulk_1d(uint32_t dst_smem, const void* src,
                                            uint32_t bytes, uint32_t mbar) {
    asm volatile(
        "cp.async.bulk.shared::cluster.global.mbarrier::complete_tx::bytes "
        "[%0], [%1], %2, [%3];"
        :: "r"(dst_smem), "l"(src), "r"(bytes), "r"(mbar) : "memory");
}

// ---------------------------------------------------------------------------
// Prep: relayout R into R_pad[p][r][w*VSTRIDE + v] with 1/sqrt(df) folded in.
// ---------------------------------------------------------------------------
__global__ void prep_kernel(const float* __restrict__ R)
{
    const float norms[NPATH] = {
        1.0f, 0.57735026918962576f, 0.44721359549995794f,
        0.57735026918962576f, 1.0f, 0.57735026918962576f,
        0.44721359549995794f, 0.57735026918962576f,
        0.44721359549995794f, 0.37796447300922723f,
        0.44721359549995794f, 0.57735026918962576f,
        0.44721359549995794f, 0.37796447300922723f, 1.0f,
        0.57735026918962576f, 0.44721359549995794f,
        0.37796447300922723f, 0.33333333333333333f
    };
    int idx = blockIdx.x * blockDim.x + threadIdx.x;
    if (idx >= NPATH * RBUF) return;
    int p    = idx / RBUF,   rem  = idx - p * RBUF;
    int r    = rem / RSLICE; int rem2 = rem - r * RSLICE;
    int w    = rem2 / VSTRIDE, v = rem2 - w * VSTRIDE;
    float val = 0.f;
    if (v < 16)
        val = R[(size_t)r * P_TOTAL + p * 256 + w * 16 + v] * norms[p];
    R_pad[idx] = val;
}

// ---------------------------------------------------------------------------
// One path, f32x2-packed. radS is non-duplicated [r][j]: one broadcast
// LDS.128 per r feeds all 4 edges; duplication happens in registers
// (mov.b64 {x,x}, ALU pipe) instead of a second LDS.
// ---------------------------------------------------------------------------
template<int IO, int II, int LF, int CGOFF>
__device__ __forceinline__ void do_path(
    const u64 (&FAB)[9],
    const float* __restrict__ Ys_p,
    const float* __restrict__ Rt,
    float* __restrict__ tmp_w,
    const float* __restrict__ radS_w,
    int m, int eh, int lA, int lB, int leA,
    u64 (&acc)[4][5])
{
    constexpr int DOUT = 2 * IO + 1;
    constexpr int DI   = 2 * II + 1;
    constexpr int DF   = 2 * LF + 1;
    constexpr int FB0  = (II == 0) ? 0 : ((II == 1) ? 1 : 4);
    constexpr int YB   = (LF == 0) ? 0 : (LF == 1) ? 4 : (LF == 2) ? 12
                       : (LF == 3) ? 20 : 28;

    // ---- packed Ys ----
    u64 yAB[DF];
    {
        float ya[DF], yb[DF];
        const float* pa = Ys_p + lA * YS_STR + YB;
        const float* pb = Ys_p + lB * YS_STR + YB;
#pragma unroll
        for (int f4 = 0; f4 < DF / 4; f4++) {
            float4 qa = *(const float4*)(pa + 4 * f4);
            float4 qb = *(const float4*)(pb + 4 * f4);
            ya[4*f4+0]=qa.x; ya[4*f4+1]=qa.y; ya[4*f4+2]=qa.z; ya[4*f4+3]=qa.w;
            yb[4*f4+0]=qb.x; yb[4*f4+1]=qb.y; yb[4*f4+2]=qb.z; yb[4*f4+3]=qb.w;
        }
#pragma unroll
        for (int f = (DF / 4) * 4; f < DF; f++) { ya[f] = pa[f]; yb[f] = pb[f]; }
#pragma unroll
        for (int f = 0; f < DF; f++) yAB[f] = pack2(ya[f], yb[f]);
    }

    // ---- packed tmp[v=m][o] for the (A,B) pair ----
    u64 tAB[DOUT];
#pragma unroll
    for (int o = 0; o < DOUT; o++) tAB[o] = 0ull;

#pragma unroll
    for (int f = 0; f < DF; f++) {
#pragma unroll
        for (int o = 0; o < DOUT; o++) {
            float c0 = cg_c[CGOFF + (o * DI + 0) * DF + f];
            u64 g = fmul2(FAB[FB0], pack2(c0, c0));
#pragma unroll
            for (int i = 1; i < DI; i++) {
                float c = cg_c[CGOFF + (o * DI + i) * DF + f];
                g = ffma2(FAB[FB0 + i], pack2(c, c), g);
            }
            tAB[o] = ffma2(yAB[f], g, tAB[o]);
        }
    }

    // ---- publish tmp scalars to warp scratch ----
    __syncwarp();
#pragma unroll
    for (int o = 0; o < DOUT; o++) {
        float lo, hi; unpack2(tAB[o], lo, hi);
        tmp_w[ leA      * TMP_ESTR + o * 16 + m] = lo;
        tmp_w[(leA + 1) * TMP_ESTR + o * 16 + m] = hi;
    }
    __syncwarp();

    // ---- W: r-outer; ONE radS LDS.128 per r (broadcast), dup in registers --
    const float* row = Rt + m * VSTRIDE + eh * 8;
    u64 wP[4][2][2];
#pragma unroll
    for (int j = 0; j < 4; j++)
#pragma unroll
        for (int g = 0; g < 2; g++) { wP[j][g][0] = 0ull; wP[j][g][1] = 0ull; }

#pragma unroll
    for (int r = 0; r < N_RBF; r++) {
        float4 rd = *(const float4*)(radS_w + r * 4);   // (rad_j0..rad_j3)
        u64 d0 = pack2(rd.x, rd.x);
        u64 d1 = pack2(rd.y, rd.y);
        u64 d2 = pack2(rd.z, rd.z);
        u64 d3 = pack2(rd.w, rd.w);
        float4 q0 = *(const float4*)(row + r * RSLICE);
        float4 q1 = *(const float4*)(row + r * RSLICE + 4);
        u64 q00 = pack2(q0.x, q0.y), q01 = pack2(q0.z, q0.w);
        u64 q10 = pack2(q1.x, q1.y), q11 = pack2(q1.z, q1.w);
        wP[0][0][0] = ffma2(d0, q00, wP[0][0][0]);
        wP[0][0][1] = ffma2(d0, q01, wP[0][0][1]);
        wP[0][1][0] = ffma2(d0, q10, wP[0][1][0]);
        wP[0][1][1] = ffma2(d0, q11, wP[0][1][1]);
        wP[1][0][0] = ffma2(d1, q00, wP[1][0][0]);
        wP[1][0][1] = ffma2(d1, q01, wP[1][0][1]);
        wP[1][1][0] = ffma2(d1, q10, wP[1][1][0]);
        wP[1][1][1] = ffma2(d1, q11, wP[1][1][1]);
        wP[2][0][0] = ffma2(d2, q00, wP[2][0][0]);
        wP[2][0][1] = ffma2(d2, q01, wP[2][0][1]);
        wP[2][1][0] = ffma2(d2, q10, wP[2][1][0]);
        wP[2][1][1] = ffma2(d2, q11, wP[2][1][1]);
        wP[3][0][0] = ffma2(d3, q00, wP[3][0][0]);
        wP[3][0][1] = ffma2(d3, q01, wP[3][0][1]);
        wP[3][1][0] = ffma2(d3, q10, wP[3][1][0]);
        wP[3][1][1] = ffma2(d3, q11, wP[3][1][1]);
    }

    // ---- apply ----
#pragma unroll
    for (int g = 0; g < 2; g++) {
        const int v0 = eh * 8 + g * 4;
#pragma unroll
        for (int j = 0; j < 4; j++) {
#pragma unroll
            for (int o = 0; o < DOUT; o++) {
                float4 tf = *(const float4*)(tmp_w + j * TMP_ESTR + o * 16 + v0);
                u64 t01 = pack2(tf.x, tf.y), t23 = pack2(tf.z, tf.w);
                acc[j][o] = ffma2(wP[j][g][0], t01, acc[j][o]);
                acc[j][o] = ffma2(wP[j][g][1], t23, acc[j][o]);
            }
        }
    }
}

// ---------------------------------------------------------------------------
__global__ void __launch_bounds__(THREADS, 2)
conv_kernel(const float* __restrict__ features,
            const float* __restrict__ Ys,
            const float* __restrict__ radii,
            const float* __restrict__ n_norm,
            const int*   __restrict__ map_a,
            const int*   __restrict__ map_b,
            float* __restrict__ out)
{
    __shared__ __align__(16) float Rt[3][RBUF];           // 38.4 kB
    __shared__ __align__(16) float tmp_s[NWARP * TMP_WARP];
    __shared__ __align__(16) float Ys_p[TILE_E * YS_STR];
    __shared__ __align__(16) float radS[NWARP * RADS_WARP]; // [warp][r][j]
    __shared__ __align__(8)  u64   mbar[3];               // ring mbarriers

    const int tid  = threadIdx.x;
    const int warp = tid >> 5;
    const int lane = tid & 31;
    const int m    = lane & 15;
    const int eh   = lane >> 4;
    const int e0   = blockIdx.x * TILE_E;
    const int leA  = eh * 2;
    const int lA   = warp * 4 + leA;
    const int lB   = lA + 1;
    float* tmp_w   = tmp_s + warp * TMP_WARP;
    const float* radS_w = radS + warp * RADS_WARP;

    const uint32_t rt_sm   = (uint32_t)__cvta_generic_to_shared(&Rt[0][0]);
    const uint32_t mbar_sm = (uint32_t)__cvta_generic_to_shared(&mbar[0]);

    // TMA bulk staging of one full path slice (12.8 kB), single thread.
#define TMA_ISSUE(P)                                                           \
    do {                                                                       \
        uint32_t mb = mbar_sm + (uint32_t)(((P) % 3) * 8);                     \
        mbar_expect_tx(mb, RBYTES);                                            \
        tma_bulk_1d(rt_sm + (uint32_t)(((P) % 3) * RBYTES),                    \
                    R_pad + (size_t)(P) * RBUF, RBYTES, mb);                   \
    } while (0)

    // ---- init mbarriers (count=1: tid0's expect_tx is the only arrival) ----
    if (tid == 0) {
        mbar_init(mbar_sm,      1);
        mbar_init(mbar_sm + 8,  1);
        mbar_init(mbar_sm + 16, 1);
    }
    __syncthreads();                 // init visible before any wait/arm
    if (tid == 0) { TMA_ISSUE(0); TMA_ISSUE(1); }

    // ---- stage padded Ys ----
    for (int idx = tid; idx < TILE_E * 25; idx += THREADS) {
        int le = idx / 25, f = idx - le * 25;
        int e  = e0 + le;
        int off = (f < 1) ? f : (f < 4) ? 3 + f : (f < 9) ? 8 + f
                : (f < 16) ? 11 + f : 12 + f;
        Ys_p[le * YS_STR + off] = (e < N_EDGES) ? Ys[(size_t)e * 25 + f] : 0.f;
    }

    // ---- per-warp radial table, NON-dup: radS[warp][r*4 + j] ----
    for (int idx = lane; idx < RADS_WARP; idx += 32) {
        int r = idx >> 2, j = idx & 3;
        int e = e0 + warp * 4 + j;
        bool v = (e < N_EDGES);
        radS[warp * RADS_WARP + idx] =
            v ? radii[(size_t)(v ? e : 0) * N_RBF + r] : 0.f;
    }

    // ---- per-lane bindings ----
    const int eA = e0 + lA, eB = e0 + lB;
    const bool vA = (eA < N_EDGES), vB = (eB < N_EDGES);
    const int eAc = vA ? eA : 0, eBc = vB ? eB : 0;

    u64 FAB[9];
    {
        const float* fA = features + (size_t)map_b[eAc] * FEAT;
        const float* fB = features + (size_t)map_b[eBc] * FEAT;
        FAB[0] = pack2(fA[m], fB[m]);
#pragma unroll
        for (int i = 0; i < 3; i++)
            FAB[1 + i] = pack2(fA[16 + m * 3 + i], fB[16 + m * 3 + i]);
#pragma unroll
        for (int i = 0; i < 5; i++)
            FAB[4 + i] = pack2(fA[64 + m * 5 + i], fB[64 + m * 5 + i]);
    }

    const int   aA  = map_a[eAc];
    const int   aB  = map_a[eBc];
    const float nnA = vA ? n_norm[aA] : 0.f;
    const float nnB = vB ? n_norm[aB] : 0.f;

    u64 acc[4][5];
#pragma unroll
    for (int j = 0; j < 4; j++)
#pragma unroll
        for (int o = 0; o < 5; o++) acc[j][o] = 0ull;

    __syncthreads();   // Ys_p, radS visible

    // STEP P: wait FULL(slot P%3, parity (P/3)&1) -> barrier (all warps done
    // reading slot (P+2)%3 from path P-1) -> tid0 arms+issues path P+2 ->
    // compute path P.
#define STEP(P, IO, II, LF, CGOFF)                                             \
    do {                                                                       \
        mbar_wait(mbar_sm + (uint32_t)(((P) % 3) * 8), ((P) / 3) & 1);         \
        __syncthreads();                                                       \
        if ((P) < 17 && tid == 0) TMA_ISSUE((P) + 2);                          \
        do_path<IO, II, LF, CGOFF>(FAB, Ys_p, Rt[(P) % 3], tmp_w,              \
                                   radS_w, m, eh, lA, lB, leA, acc);           \
    } while (0)

#define EMIT(DOUT, EXPR_IDX)                                                   \
    do {                                                                       \
        float tot[4][DOUT];                                                    \
        _Pragma("unroll")                                                      \
        for (int j = 0; j < 4; j++)                                            \
            _Pragma("unroll")                                                  \
            for (int o = 0; o < (DOUT); o++) {                                 \
                u64 s = fadd2(acc[j][o],                                       \
                              __shfl_xor_sync(0xffffffffu, acc[j][o], 16));    \
                float lo, hi; unpack2(s, lo, hi);                              \
                tot[j][o] = lo + hi;                                           \
            }                                                                  \
        _Pragma("unroll")                                                      \
        for (int o = 0; o < (DOUT); o++) {                                     \
            if (vA) atomicAdd(&out[(size_t)aA * FEAT + (EXPR_IDX)],            \
                              nnA * tot[leA][o]);                              \
            if (vB) atomicAdd(&out[(size_t)aB * FEAT + (EXPR_IDX)],            \
                              nnB * tot[leA + 1][o]);                          \
        }                                                                      \
    } while (0)

#define CLEAR()                                                                \
    do {                                                                       \
        _Pragma("unroll")                                                      \
        for (int j = 0; j < 4; j++)                                            \
            _Pragma("unroll")                                                  \
            for (int o = 0; o < 5; o++) acc[j][o] = 0ull;                      \
    } while (0)

    // ---------------- io = 0 (DOUT = 1, out offset 0) -----------------------
    STEP(0, 0, 0, 0, 0);
    STEP(1, 0, 1, 1, 1);
    STEP(2, 0, 2, 2, 10);
    EMIT(1, m);
    CLEAR();

    // ---------------- io = 1 (DOUT = 3, out offset 16) ----------------------
    STEP(3, 1, 0, 1, 35);
    STEP(4, 1, 1, 0, 44);
    STEP(5, 1, 1, 1, 53);
    STEP(6, 1, 1, 2, 80);
    STEP(7, 1, 2, 1, 125);
    STEP(8, 1, 2, 2, 170);
    STEP(9, 1, 2, 3, 245);
    EMIT(3, 16 + m * 3 + o);
    CLEAR();

    // ---------------- io = 2 (DOUT = 5, out offset 64) ----------------------
    STEP(10, 2, 0, 2, 350);
    STEP(11, 2, 1, 1, 375);
    STEP(12, 2, 1, 2, 420);
    STEP(13, 2, 1, 3, 495);
    STEP(14, 2, 2, 0, 600);
    STEP(15, 2, 2, 1, 625);
    STEP(16, 2, 2, 2, 700);
    STEP(17, 2, 2, 3, 825);
    STEP(18, 2, 2, 4, 1000);
    EMIT(5, 64 + m * 5 + o);

#undef STEP
#undef EMIT
#undef CLEAR
#undef TMA_ISSUE
}

// ---------------------------------------------------------------------------
extern "C" void kernel_launch(void* const* d_in, const int* in_sizes, int n_in,
                              void* d_out, int out_size)
{
    const float* features = (const float*)d_in[0];
    const float* R        = (const float*)d_in[1];
    const float* Ys       = (const float*)d_in[2];
    const float* radii    = (const float*)d_in[3];
    const float* cg       = (const float*)d_in[4];
    const float* n_norm   = (const float*)d_in[5];
    const int*   map_a    = (const int*)d_in[6];
    const int*   map_b    = (const int*)d_in[7];
    float*       out      = (float*)d_out;

    cudaMemcpyToSymbolAsync(cg_c, cg, 1225 * sizeof(float), 0,
                            cudaMemcpyDeviceToDevice, 0);
    cudaMemsetAsync(out, 0, (size_t)out_size * sizeof(float));

    prep_kernel<<<(NPATH * RBUF + 255) / 256, 256>>>(R);

    int grid = (N_EDGES + TILE_E - 1) / TILE_E;   // 7813
    conv_kernel<<<grid, THREADS>>>(features, Ys, radii, n_norm,
                                   map_a, map_b, out);
}